// round 1
// baseline (speedup 1.0000x reference)
#include <cuda_runtime.h>
#include <math.h>

#define BB 2
#define CC 256
#define TT 400
#define FF 256
#define KK 32
#define EPSV 1e-6f

// ---------------- scratch (static device globals; allocation-free) ----------
__device__ float g_invrms [BB*TT*FF];                    // per (b,t,f) inv rms of x
__device__ float g_emb0   [(size_t)BB*CC*TT*FF];         // after pre pw
__device__ float g_kbuf   [(size_t)BB*CC*TT*FF];
__device__ float g_vbuf   [(size_t)BB*CC*TT*FF];
__device__ float g_qseed  [(size_t)BB*CC*TT*KK];
__device__ float g_qbuf   [(size_t)BB*CC*TT*KK];
__device__ float g_scores [(size_t)BB*TT*KK*FF];         // scores then weights (in place)
__device__ float g_att    [(size_t)BB*CC*TT*KK];
__device__ float g_hidden [(size_t)BB*CC*TT*KK];
__device__ float g_hffn   [(size_t)BB*2*CC*TT*KK];
__device__ float g_glu    [(size_t)BB*CC*TT*KK];
__device__ float g_invrms2[BB*TT*KK];

// ---------------- kernel 1: inv rms of x over channel dim -------------------
__global__ void rms1_kernel(const float* __restrict__ x) {
    int bt = blockIdx.x;                 // b*TT + t
    int f  = threadIdx.x;                // 0..FF-1
    int b = bt / TT, t = bt % TT;
    size_t base = ((size_t)b * CC * TT + t) * FF + f;
    float s = 0.f;
    #pragma unroll 4
    for (int c = 0; c < CC; c++) {
        float v = x[base + (size_t)c * TT * FF];
        s += v * v;
    }
    g_invrms[bt * FF + f] = rsqrtf(s * (1.f / CC) + EPSV);
}

// ---------------- generic per-frame pointwise GEMM --------------------------
// Y[b,o,t,n] = sum_c W[o,c] * X[b,c,t,n] * colscale(bt,n) * rowscale(c) + bias[o] (+ addsrc)
// Tiles: BM=64 x BN, BK=16, thread tile 4 x TN, block (16,16).
template<int BN, int TN>
__global__ void frame_gemm(const float* __restrict__ W, const float* __restrict__ bias,
                           const float* __restrict__ X, float* __restrict__ Y,
                           const float* __restrict__ colscale,
                           const float* __restrict__ rowscale,
                           const float* __restrict__ addsrc,
                           int Cin, int Cout, int N) {
    const int BM = 64, BK = 16;
    __shared__ float Ws[BK][BM + 4];
    __shared__ float Xs[BK][BN + 4];

    int bt = blockIdx.z;
    int b = bt / TT, t = bt % TT;
    size_t xframe = ((size_t)b * Cin  * TT + t) * N;
    size_t yframe = ((size_t)b * Cout * TT + t) * N;
    int n0 = blockIdx.x * BN;
    int o0 = blockIdx.y * BM;
    int tx = threadIdx.x, ty = threadIdx.y;
    int tid = ty * 16 + tx;

    float acc[4][TN];
    #pragma unroll
    for (int i = 0; i < 4; i++)
        #pragma unroll
        for (int j = 0; j < TN; j++) acc[i][j] = 0.f;

    for (int c0 = 0; c0 < Cin; c0 += BK) {
        // W tile (BM x BK)
        #pragma unroll
        for (int e = tid; e < BM * BK; e += 256) {
            int r = e / BK, cc = e % BK;
            Ws[cc][r] = W[(size_t)(o0 + r) * Cin + c0 + cc];
        }
        // X tile (BK x BN)
        #pragma unroll
        for (int e = tid; e < BK * BN; e += 256) {
            int cr = e / BN, nn = e % BN;
            float v = X[xframe + (size_t)(c0 + cr) * TT * N + n0 + nn];
            if (colscale) v *= colscale[(size_t)bt * N + n0 + nn];
            if (rowscale) v *= rowscale[c0 + cr];
            Xs[cr][nn] = v;
        }
        __syncthreads();
        #pragma unroll
        for (int kk = 0; kk < BK; kk++) {
            float rm[4], rn[TN];
            #pragma unroll
            for (int i = 0; i < 4; i++) rm[i] = Ws[kk][ty * 4 + i];
            #pragma unroll
            for (int j = 0; j < TN; j++) rn[j] = Xs[kk][tx * TN + j];
            #pragma unroll
            for (int i = 0; i < 4; i++)
                #pragma unroll
                for (int j = 0; j < TN; j++) acc[i][j] += rm[i] * rn[j];
        }
        __syncthreads();
    }
    #pragma unroll
    for (int i = 0; i < 4; i++) {
        int o = o0 + ty * 4 + i;
        float bv = bias ? bias[o] : 0.f;
        #pragma unroll
        for (int j = 0; j < TN; j++) {
            int n = n0 + tx * TN + j;
            size_t yi = yframe + (size_t)o * TT * N + n;
            float v = acc[i][j] + bv;
            if (addsrc) v += addsrc[yi];
            Y[yi] = v;
        }
    }
}

// ---------------- depthwise 3x3 causal conv + SiLU --------------------------
__global__ void dwconv_kernel(const float* __restrict__ dww, const float* __restrict__ dwb,
                              float* __restrict__ emb) {
    long idx = blockIdx.x;               // (b*CC + c)*TT + t
    int t = (int)(idx % TT);
    long bc = idx / TT;
    int c = (int)(bc % CC);
    int f = threadIdx.x;
    __shared__ float rows[3][FF + 2];
    size_t chbase = (size_t)bc * TT * FF;
    #pragma unroll
    for (int dt = 0; dt < 3; dt++) {
        int tt = t - 2 + dt;
        rows[dt][f + 1] = (tt >= 0) ? g_emb0[chbase + (size_t)tt * FF + f] : 0.f;
        if (f == 0) { rows[dt][0] = 0.f; rows[dt][FF + 1] = 0.f; }
    }
    __syncthreads();
    float w[9];
    #pragma unroll
    for (int i = 0; i < 9; i++) w[i] = dww[c * 9 + i];
    float s = dwb[c];
    #pragma unroll
    for (int dt = 0; dt < 3; dt++)
        #pragma unroll
        for (int df = 0; df < 3; df++)
            s += w[dt * 3 + df] * rows[dt][f + df];
    s = s / (1.f + __expf(-s));  // SiLU
    emb[chbase + (size_t)t * FF + f] = s;
}

// ---------------- per-frame A(CxF) * B(KxF)^T -> Y(CxK) ----------------------
// Used for qseed (B=basis, bStride=0) and attended (B=weights frame, bStride=K*F)
__global__ void gemm_abT_kernel(const float* __restrict__ A, const float* __restrict__ Bm,
                                long bStride, float* __restrict__ Y) {
    __shared__ float As[256][33];
    __shared__ float Bs[32][33];
    int bt = blockIdx.x;
    int b = bt / TT, t = bt % TT;
    size_t aframe = ((size_t)b * CC * TT + t) * FF;
    size_t yframe = ((size_t)b * CC * TT + t) * KK;
    const float* Bp = Bm + (size_t)bt * bStride;
    int tid = threadIdx.x;

    float acc[KK];
    #pragma unroll
    for (int k = 0; k < KK; k++) acc[k] = 0.f;

    for (int fc = 0; fc < FF; fc += 32) {
        #pragma unroll
        for (int i = 0; i < 32; i++) {
            int e = i * 256 + tid;
            int c = e >> 5, ff = e & 31;
            As[c][ff] = A[aframe + (size_t)c * TT * FF + fc + ff];
        }
        #pragma unroll
        for (int i = 0; i < 4; i++) {
            int e = i * 256 + tid;
            int k = e >> 5, ff = e & 31;
            Bs[ff][k] = Bp[(size_t)k * FF + fc + ff];
        }
        __syncthreads();
        #pragma unroll
        for (int ff = 0; ff < 32; ff++) {
            float av = As[tid][ff];
            #pragma unroll
            for (int k = 0; k < KK; k++) acc[k] += av * Bs[ff][k];
        }
        __syncthreads();
    }
    // stage for coalesced store
    #pragma unroll
    for (int k = 0; k < KK; k++) As[tid][k] = acc[k];
    __syncthreads();
    #pragma unroll
    for (int i = 0; i < 32; i++) {
        int e = i * 256 + tid;
        int c = e >> 5, k = e & 31;
        Y[yframe + (size_t)c * TT * KK + k] = As[c][k];
    }
}

// ---------------- scores: per frame q(CxK)^T * k(CxF) + bias ----------------
__global__ void scores_kernel(const float* __restrict__ Q, const float* __restrict__ Kb,
                              const float* __restrict__ rb,
                              const float* __restrict__ ss, const float* __restrict__ ps,
                              float* __restrict__ S) {
    __shared__ float qs[256][33];
    int bt = blockIdx.x;
    int b = bt / TT, t = bt % TT;
    size_t qframe = ((size_t)b * CC * TT + t) * KK;
    size_t kframe = ((size_t)b * CC * TT + t) * FF;
    int tid = threadIdx.x;
    #pragma unroll
    for (int i = 0; i < 32; i++) {
        int e = i * 256 + tid;
        int c = e >> 5, k = e & 31;
        qs[c][k] = Q[qframe + (size_t)c * TT * KK + k];
    }
    __syncthreads();
    int f = tid;
    float acc[KK];
    #pragma unroll
    for (int k = 0; k < KK; k++) acc[k] = 0.f;
    for (int c = 0; c < CC; c++) {
        float kv = Kb[kframe + (size_t)c * TT * FF + f];
        #pragma unroll
        for (int k = 0; k < KK; k++) acc[k] += qs[c][k] * kv;
    }
    float scale = *ss, pscale = *ps;
    #pragma unroll
    for (int k = 0; k < KK; k++)
        S[((size_t)bt * KK + k) * FF + f] = acc[k] * scale + rb[k * FF + f] * pscale;
}

// ---------------- softmax over F, in place -----------------------------------
__global__ void softmax_kernel(float* __restrict__ S) {
    int row = blockIdx.x;                // bt*KK + k
    int tid = threadIdx.x;
    __shared__ float red[8];
    float v = S[(size_t)row * FF + tid];
    float m = v;
    #pragma unroll
    for (int o = 16; o; o >>= 1) m = fmaxf(m, __shfl_xor_sync(0xffffffffu, m, o));
    if ((tid & 31) == 0) red[tid >> 5] = m;
    __syncthreads();
    float bm = fmaxf(fmaxf(fmaxf(red[0], red[1]), fmaxf(red[2], red[3])),
                     fmaxf(fmaxf(red[4], red[5]), fmaxf(red[6], red[7])));
    float e = __expf(v - bm);
    float s = e;
    #pragma unroll
    for (int o = 16; o; o >>= 1) s += __shfl_xor_sync(0xffffffffu, s, o);
    __syncthreads();
    if ((tid & 31) == 0) red[tid >> 5] = s;
    __syncthreads();
    float bs = red[0] + red[1] + red[2] + red[3] + red[4] + red[5] + red[6] + red[7];
    S[(size_t)row * FF + tid] = e / bs;
}

// ---------------- inv rms of hidden over channels -----------------------------
__global__ void rms2_kernel() {
    int k = threadIdx.x;
    int bt = blockIdx.x * blockDim.y + threadIdx.y;
    int b = bt / TT, t = bt % TT;
    size_t base = ((size_t)b * CC * TT + t) * KK + k;
    float s = 0.f;
    #pragma unroll 4
    for (int c = 0; c < CC; c++) {
        float v = g_hidden[base + (size_t)c * TT * KK];
        s += v * v;
    }
    g_invrms2[bt * KK + k] = rsqrtf(s * (1.f / CC) + EPSV);
}

// ---------------- GLU: a * silu(b) --------------------------------------------
__global__ void glu_kernel() {
    long i = (long)blockIdx.x * blockDim.x + threadIdx.x;   // over B*C*T*K
    const long CTK = (long)CC * TT * KK;
    long b = i / CTK, r = i % CTK;
    float a  = g_hffn[b * 2 * CTK + r];
    float bb = g_hffn[b * 2 * CTK + CTK + r];
    g_glu[i] = a * (bb / (1.f + __expf(-bb)));
}

// ---------------- host launcher ------------------------------------------------
extern "C" void kernel_launch(void* const* d_in, const int* in_sizes, int n_in,
                              void* d_out, int out_size) {
    const float* x          = (const float*)d_in[0];
    const float* pre_norm_w = (const float*)d_in[1];
    const float* pre_pw_w   = (const float*)d_in[2];
    const float* pre_pw_b   = (const float*)d_in[3];
    const float* pre_dw_w   = (const float*)d_in[4];
    const float* pre_dw_b   = (const float*)d_in[5];
    const float* q_w        = (const float*)d_in[6];
    const float* q_b        = (const float*)d_in[7];
    const float* k_w        = (const float*)d_in[8];
    const float* k_b        = (const float*)d_in[9];
    const float* v_w        = (const float*)d_in[10];
    const float* v_b        = (const float*)d_in[11];
    const float* out_w      = (const float*)d_in[12];
    const float* out_b      = (const float*)d_in[13];
    const float* ffn_norm_w = (const float*)d_in[14];
    const float* ffn_in_w   = (const float*)d_in[15];
    const float* ffn_in_b   = (const float*)d_in[16];
    const float* ffn_out_w  = (const float*)d_in[17];
    const float* ffn_out_b  = (const float*)d_in[18];
    const float* score_scale= (const float*)d_in[19];
    const float* prior_scale= (const float*)d_in[20];
    const float* query_basis= (const float*)d_in[21];
    const float* routing_bias=(const float*)d_in[22];

    float* out       = (float*)d_out;
    float* out_hidden= out;                                   // [B,C,T,K]
    float* out_emb   = out + (size_t)BB * CC * TT * KK;       // [B,C,T,F]

    float *emb0, *kbuf, *vbuf, *qseed, *qbuf, *scores, *att, *hidden, *hffn, *glu, *invrms, *invrms2;
    cudaGetSymbolAddress((void**)&emb0,    g_emb0);
    cudaGetSymbolAddress((void**)&kbuf,    g_kbuf);
    cudaGetSymbolAddress((void**)&vbuf,    g_vbuf);
    cudaGetSymbolAddress((void**)&qseed,   g_qseed);
    cudaGetSymbolAddress((void**)&qbuf,    g_qbuf);
    cudaGetSymbolAddress((void**)&scores,  g_scores);
    cudaGetSymbolAddress((void**)&att,     g_att);
    cudaGetSymbolAddress((void**)&hidden,  g_hidden);
    cudaGetSymbolAddress((void**)&hffn,    g_hffn);
    cudaGetSymbolAddress((void**)&glu,     g_glu);
    cudaGetSymbolAddress((void**)&invrms,  g_invrms);
    cudaGetSymbolAddress((void**)&invrms2, g_invrms2);

    dim3 blk(16, 16);
    const int NBT = BB * TT;  // 800

    // 1. inv rms of x
    rms1_kernel<<<NBT, FF>>>(x);
    // 2. pre pw: emb0 = W @ rmsnorm(x)
    frame_gemm<64,4><<<dim3(FF/64, CC/64, NBT), blk>>>(pre_pw_w, pre_pw_b, x, emb0,
                                                       invrms, pre_norm_w, nullptr, CC, CC, FF);
    // 3. depthwise conv + SiLU -> emb (directly into d_out)
    dwconv_kernel<<<BB*CC*TT, FF>>>(pre_dw_w, pre_dw_b, out_emb);
    // 4/5. k, v projections
    frame_gemm<64,4><<<dim3(FF/64, CC/64, NBT), blk>>>(k_w, k_b, out_emb, kbuf,
                                                       nullptr, nullptr, nullptr, CC, CC, FF);
    frame_gemm<64,4><<<dim3(FF/64, CC/64, NBT), blk>>>(v_w, v_b, out_emb, vbuf,
                                                       nullptr, nullptr, nullptr, CC, CC, FF);
    // 6. query seed: basis pooling
    gemm_abT_kernel<<<NBT, 256>>>(out_emb, query_basis, 0, qseed);
    // 7. q projection
    frame_gemm<32,2><<<dim3(1, CC/64, NBT), blk>>>(q_w, q_b, qseed, qbuf,
                                                   nullptr, nullptr, nullptr, CC, CC, KK);
    // 8. scores
    scores_kernel<<<NBT, 256>>>(qbuf, kbuf, routing_bias, score_scale, prior_scale, scores);
    // 9. softmax over F (in place)
    softmax_kernel<<<NBT * KK, FF>>>(scores);
    // 10. attended
    gemm_abT_kernel<<<NBT, 256>>>(vbuf, scores, (long)KK * FF, att);
    // 11. out projection -> hidden
    frame_gemm<32,2><<<dim3(1, CC/64, NBT), blk>>>(out_w, out_b, att, hidden,
                                                   nullptr, nullptr, nullptr, CC, CC, KK);
    // 12. inv rms of hidden
    rms2_kernel<<<NBT/8, dim3(KK, 8)>>>();
    // 13. ffn_in (2C outputs) on rmsnorm(hidden)
    frame_gemm<32,2><<<dim3(1, 2*CC/64, NBT), blk>>>(ffn_in_w, ffn_in_b, hidden, hffn,
                                                     invrms2, ffn_norm_w, nullptr, CC, 2*CC, KK);
    // 14. GLU
    glu_kernel<<<(BB*CC*TT*KK)/256, 256>>>();
    // 15. ffn_out + residual -> final hidden into d_out
    frame_gemm<32,2><<<dim3(1, CC/64, NBT), blk>>>(ffn_out_w, ffn_out_b, glu, out_hidden,
                                                   nullptr, nullptr, hidden, CC, CC, KK);
}

// round 2
// speedup vs baseline: 2.6952x; 2.6952x over previous
#include <cuda_runtime.h>
#include <math.h>

#define BB 2
#define CC 256
#define TT 400
#define FF 256
#define KK 32
#define EPSV 1e-6f

// ---------------- scratch (static device globals; allocation-free) ----------
__device__ float g_invrms [BB*TT*FF];
__device__ float g_emb0   [(size_t)BB*CC*TT*FF];
__device__ float g_kbuf   [(size_t)BB*CC*TT*FF];
__device__ float g_vbuf   [(size_t)BB*CC*TT*FF];
__device__ float g_qseed  [(size_t)BB*CC*TT*KK];
__device__ float g_qbuf   [(size_t)BB*CC*TT*KK];
__device__ float g_scores [(size_t)BB*TT*KK*FF];
__device__ float g_att    [(size_t)BB*CC*TT*KK];
__device__ float g_hidden [(size_t)BB*CC*TT*KK];
__device__ float g_hffn   [(size_t)BB*2*CC*TT*KK];
__device__ float g_glu    [(size_t)BB*CC*TT*KK];
__device__ float g_invrms2[BB*TT*KK];

// ---------------- tf32 helpers ----------------------------------------------
__device__ __forceinline__ unsigned f2tf32(float f) {
    unsigned r;
    asm("cvt.rna.tf32.f32 %0, %1;" : "=r"(r) : "f"(f));
    return r;
}

__device__ __forceinline__ void mma_tf32(float* c, const unsigned* a, const unsigned* b) {
    asm volatile(
        "mma.sync.aligned.m16n8k8.row.col.f32.tf32.tf32.f32 "
        "{%0,%1,%2,%3}, {%4,%5,%6,%7}, {%8,%9}, {%0,%1,%2,%3};\n"
        : "+f"(c[0]), "+f"(c[1]), "+f"(c[2]), "+f"(c[3])
        : "r"(a[0]), "r"(a[1]), "r"(a[2]), "r"(a[3]), "r"(b[0]), "r"(b[1]));
}

// ---------------- batched pointwise GEMM on tensor cores ---------------------
// Y[b,o,n] = sum_c W[o,c] * X[b,c,n] * colscale[b,n] * rowscale[c] + bias[o] (+addsrc)
// Block tile 128x128x32, 8 warps (4 x 2), warp tile 32x64, mma m16n8k8 tf32.
__global__ void __launch_bounds__(256, 2)
gemm_tf32(const float* __restrict__ W, const float* __restrict__ bias,
          const float* __restrict__ X, float* __restrict__ Y,
          const float* __restrict__ colscale, const float* __restrict__ rowscale,
          const float* __restrict__ addsrc,
          int K, int Cout, int Ntot)
{
    const int BM = 128, BN = 128, BK = 32;
    __shared__ unsigned Ws[BM][BK + 4];   // [m][k]
    __shared__ unsigned Xs[BK][BN + 4];   // [k][n]

    int b  = blockIdx.z;
    int n0 = blockIdx.x * BN;
    int o0 = blockIdx.y * BM;
    const float* Xb = X + (size_t)b * K * Ntot;
    float*       Yb = Y + (size_t)b * Cout * Ntot;
    const float* As = addsrc ? addsrc + (size_t)b * Cout * Ntot : nullptr;
    const float* cs = colscale ? colscale + (size_t)b * Ntot : nullptr;

    int tid  = threadIdx.x;
    int warp = tid >> 5, lane = tid & 31;
    int wm = warp & 3, wn = warp >> 2;     // 4 x 2 warp grid
    int group = lane >> 2, tid4 = lane & 3;

    float acc[2][8][4];
    #pragma unroll
    for (int mt = 0; mt < 2; mt++)
        #pragma unroll
        for (int nt = 0; nt < 8; nt++)
            #pragma unroll
            for (int r = 0; r < 4; r++) acc[mt][nt][r] = 0.f;

    for (int k0 = 0; k0 < K; k0 += BK) {
        // W tile: 128 x 32 (row-major), float4 global loads
        #pragma unroll
        for (int i = 0; i < 4; i++) {
            int e = i * 256 + tid;             // 0..1023 float4 slots
            int m = e >> 3;
            int kk4 = (e & 7) * 4;
            float4 v = *(const float4*)(W + (size_t)(o0 + m) * K + k0 + kk4);
            Ws[m][kk4 + 0] = f2tf32(v.x);
            Ws[m][kk4 + 1] = f2tf32(v.y);
            Ws[m][kk4 + 2] = f2tf32(v.z);
            Ws[m][kk4 + 3] = f2tf32(v.w);
        }
        // X tile: 32 x 128, rows contiguous in n; fused row/col scaling
        #pragma unroll
        for (int i = 0; i < 4; i++) {
            int e = i * 256 + tid;
            int kk = e >> 5;
            int nn4 = (e & 31) * 4;
            float4 v = *(const float4*)(Xb + (size_t)(k0 + kk) * Ntot + n0 + nn4);
            if (cs) {
                float4 s = *(const float4*)(cs + n0 + nn4);
                v.x *= s.x; v.y *= s.y; v.z *= s.z; v.w *= s.w;
            }
            if (rowscale) {
                float rs = rowscale[k0 + kk];
                v.x *= rs; v.y *= rs; v.z *= rs; v.w *= rs;
            }
            Xs[kk][nn4 + 0] = f2tf32(v.x);
            Xs[kk][nn4 + 1] = f2tf32(v.y);
            Xs[kk][nn4 + 2] = f2tf32(v.z);
            Xs[kk][nn4 + 3] = f2tf32(v.w);
        }
        __syncthreads();

        #pragma unroll
        for (int ks = 0; ks < BK; ks += 8) {
            unsigned a[2][4], bf[8][2];
            #pragma unroll
            for (int mt = 0; mt < 2; mt++) {
                int mr = wm * 32 + mt * 16 + group;
                a[mt][0] = Ws[mr    ][ks + tid4];
                a[mt][1] = Ws[mr + 8][ks + tid4];
                a[mt][2] = Ws[mr    ][ks + tid4 + 4];
                a[mt][3] = Ws[mr + 8][ks + tid4 + 4];
            }
            #pragma unroll
            for (int nt = 0; nt < 8; nt++) {
                int nc = wn * 64 + nt * 8 + group;
                bf[nt][0] = Xs[ks + tid4    ][nc];
                bf[nt][1] = Xs[ks + tid4 + 4][nc];
            }
            #pragma unroll
            for (int mt = 0; mt < 2; mt++)
                #pragma unroll
                for (int nt = 0; nt < 8; nt++)
                    mma_tf32(acc[mt][nt], a[mt], bf[nt]);
        }
        __syncthreads();
    }

    // epilogue: bias (+addsrc), float2 stores
    #pragma unroll
    for (int mt = 0; mt < 2; mt++) {
        int row = o0 + wm * 32 + mt * 16 + group;
        float bv0 = bias[row];
        float bv8 = bias[row + 8];
        #pragma unroll
        for (int nt = 0; nt < 8; nt++) {
            int col = n0 + wn * 64 + nt * 8 + tid4 * 2;
            size_t i0 = (size_t)row * Ntot + col;
            size_t i8 = (size_t)(row + 8) * Ntot + col;
            float2 v0 = make_float2(acc[mt][nt][0] + bv0, acc[mt][nt][1] + bv0);
            float2 v8 = make_float2(acc[mt][nt][2] + bv8, acc[mt][nt][3] + bv8);
            if (As) {
                float2 a0 = *(const float2*)(As + i0);
                float2 a8 = *(const float2*)(As + i8);
                v0.x += a0.x; v0.y += a0.y;
                v8.x += a8.x; v8.y += a8.y;
            }
            *(float2*)(Yb + i0) = v0;
            *(float2*)(Yb + i8) = v8;
        }
    }
}

// ---------------- kernel 1: inv rms of x over channel dim -------------------
__global__ void rms1_kernel(const float* __restrict__ x) {
    int bt = blockIdx.x;
    int f  = threadIdx.x;
    int b = bt / TT, t = bt % TT;
    size_t base = ((size_t)b * CC * TT + t) * FF + f;
    float s = 0.f;
    #pragma unroll 4
    for (int c = 0; c < CC; c++) {
        float v = x[base + (size_t)c * TT * FF];
        s += v * v;
    }
    g_invrms[bt * FF + f] = rsqrtf(s * (1.f / CC) + EPSV);
}

// ---------------- depthwise 3x3 causal conv + SiLU --------------------------
__global__ void dwconv_kernel(const float* __restrict__ dww, const float* __restrict__ dwb,
                              float* __restrict__ emb) {
    long idx = blockIdx.x;               // (b*CC + c)*TT + t
    int t = (int)(idx % TT);
    long bc = idx / TT;
    int c = (int)(bc % CC);
    int f = threadIdx.x;
    __shared__ float rows[3][FF + 2];
    size_t chbase = (size_t)bc * TT * FF;
    #pragma unroll
    for (int dt = 0; dt < 3; dt++) {
        int tt = t - 2 + dt;
        rows[dt][f + 1] = (tt >= 0) ? g_emb0[chbase + (size_t)tt * FF + f] : 0.f;
        if (f == 0) { rows[dt][0] = 0.f; rows[dt][FF + 1] = 0.f; }
    }
    __syncthreads();
    float w[9];
    #pragma unroll
    for (int i = 0; i < 9; i++) w[i] = dww[c * 9 + i];
    float s = dwb[c];
    #pragma unroll
    for (int dt = 0; dt < 3; dt++)
        #pragma unroll
        for (int df = 0; df < 3; df++)
            s += w[dt * 3 + df] * rows[dt][f + df];
    s = s / (1.f + __expf(-s));
    emb[chbase + (size_t)t * FF + f] = s;
}

// ---------------- per-frame A(CxF) * B(KxF)^T -> Y(CxK) ----------------------
__global__ void gemm_abT_kernel(const float* __restrict__ A, const float* __restrict__ Bm,
                                long bStride, float* __restrict__ Y) {
    __shared__ float As[256][33];
    __shared__ float Bs[32][33];
    int bt = blockIdx.x;
    int b = bt / TT, t = bt % TT;
    size_t aframe = ((size_t)b * CC * TT + t) * FF;
    size_t yframe = ((size_t)b * CC * TT + t) * KK;
    const float* Bp = Bm + (size_t)bt * bStride;
    int tid = threadIdx.x;

    float acc[KK];
    #pragma unroll
    for (int k = 0; k < KK; k++) acc[k] = 0.f;

    for (int fc = 0; fc < FF; fc += 32) {
        #pragma unroll
        for (int i = 0; i < 32; i++) {
            int e = i * 256 + tid;
            int c = e >> 5, ff = e & 31;
            As[c][ff] = A[aframe + (size_t)c * TT * FF + fc + ff];
        }
        #pragma unroll
        for (int i = 0; i < 4; i++) {
            int e = i * 256 + tid;
            int k = e >> 5, ff = e & 31;
            Bs[ff][k] = Bp[(size_t)k * FF + fc + ff];
        }
        __syncthreads();
        #pragma unroll
        for (int ff = 0; ff < 32; ff++) {
            float av = As[tid][ff];
            #pragma unroll
            for (int k = 0; k < KK; k++) acc[k] += av * Bs[ff][k];
        }
        __syncthreads();
    }
    #pragma unroll
    for (int k = 0; k < KK; k++) As[tid][k] = acc[k];
    __syncthreads();
    #pragma unroll
    for (int i = 0; i < 32; i++) {
        int e = i * 256 + tid;
        int c = e >> 5, k = e & 31;
        Y[yframe + (size_t)c * TT * KK + k] = As[c][k];
    }
}

// ---------------- scores: per frame q(CxK)^T * k(CxF) + bias ----------------
__global__ void scores_kernel(const float* __restrict__ Q, const float* __restrict__ Kb,
                              const float* __restrict__ rb,
                              const float* __restrict__ ss, const float* __restrict__ ps,
                              float* __restrict__ S) {
    __shared__ float qs[256][33];
    int bt = blockIdx.x;
    int b = bt / TT, t = bt % TT;
    size_t qframe = ((size_t)b * CC * TT + t) * KK;
    size_t kframe = ((size_t)b * CC * TT + t) * FF;
    int tid = threadIdx.x;
    #pragma unroll
    for (int i = 0; i < 32; i++) {
        int e = i * 256 + tid;
        int c = e >> 5, k = e & 31;
        qs[c][k] = Q[qframe + (size_t)c * TT * KK + k];
    }
    __syncthreads();
    int f = tid;
    float acc[KK];
    #pragma unroll
    for (int k = 0; k < KK; k++) acc[k] = 0.f;
    for (int c = 0; c < CC; c++) {
        float kv = Kb[kframe + (size_t)c * TT * FF + f];
        #pragma unroll
        for (int k = 0; k < KK; k++) acc[k] += qs[c][k] * kv;
    }
    float scale = *ss, pscale = *ps;
    #pragma unroll
    for (int k = 0; k < KK; k++)
        S[((size_t)bt * KK + k) * FF + f] = acc[k] * scale + rb[k * FF + f] * pscale;
}

// ---------------- softmax over F, in place -----------------------------------
__global__ void softmax_kernel(float* __restrict__ S) {
    int row = blockIdx.x;
    int tid = threadIdx.x;
    __shared__ float red[8];
    float v = S[(size_t)row * FF + tid];
    float m = v;
    #pragma unroll
    for (int o = 16; o; o >>= 1) m = fmaxf(m, __shfl_xor_sync(0xffffffffu, m, o));
    if ((tid & 31) == 0) red[tid >> 5] = m;
    __syncthreads();
    float bm = fmaxf(fmaxf(fmaxf(red[0], red[1]), fmaxf(red[2], red[3])),
                     fmaxf(fmaxf(red[4], red[5]), fmaxf(red[6], red[7])));
    float e = __expf(v - bm);
    float s = e;
    #pragma unroll
    for (int o = 16; o; o >>= 1) s += __shfl_xor_sync(0xffffffffu, s, o);
    __syncthreads();
    if ((tid & 31) == 0) red[tid >> 5] = s;
    __syncthreads();
    float bs = red[0] + red[1] + red[2] + red[3] + red[4] + red[5] + red[6] + red[7];
    S[(size_t)row * FF + tid] = e / bs;
}

// ---------------- inv rms of hidden over channels -----------------------------
__global__ void rms2_kernel() {
    int k = threadIdx.x;
    int bt = blockIdx.x * blockDim.y + threadIdx.y;
    int b = bt / TT, t = bt % TT;
    size_t base = ((size_t)b * CC * TT + t) * KK + k;
    float s = 0.f;
    #pragma unroll 4
    for (int c = 0; c < CC; c++) {
        float v = g_hidden[base + (size_t)c * TT * KK];
        s += v * v;
    }
    g_invrms2[bt * KK + k] = rsqrtf(s * (1.f / CC) + EPSV);
}

// ---------------- GLU: a * silu(b) --------------------------------------------
__global__ void glu_kernel() {
    long i = (long)blockIdx.x * blockDim.x + threadIdx.x;
    const long CTK = (long)CC * TT * KK;
    long b = i / CTK, r = i % CTK;
    float a  = g_hffn[b * 2 * CTK + r];
    float bb = g_hffn[b * 2 * CTK + CTK + r];
    g_glu[i] = a * (bb / (1.f + __expf(-bb)));
}

// ---------------- host launcher ------------------------------------------------
extern "C" void kernel_launch(void* const* d_in, const int* in_sizes, int n_in,
                              void* d_out, int out_size) {
    const float* x          = (const float*)d_in[0];
    const float* pre_norm_w = (const float*)d_in[1];
    const float* pre_pw_w   = (const float*)d_in[2];
    const float* pre_pw_b   = (const float*)d_in[3];
    const float* pre_dw_w   = (const float*)d_in[4];
    const float* pre_dw_b   = (const float*)d_in[5];
    const float* q_w        = (const float*)d_in[6];
    const float* q_b        = (const float*)d_in[7];
    const float* k_w        = (const float*)d_in[8];
    const float* k_b        = (const float*)d_in[9];
    const float* v_w        = (const float*)d_in[10];
    const float* v_b        = (const float*)d_in[11];
    const float* out_w      = (const float*)d_in[12];
    const float* out_b      = (const float*)d_in[13];
    const float* ffn_norm_w = (const float*)d_in[14];
    const float* ffn_in_w   = (const float*)d_in[15];
    const float* ffn_in_b   = (const float*)d_in[16];
    const float* ffn_out_w  = (const float*)d_in[17];
    const float* ffn_out_b  = (const float*)d_in[18];
    const float* score_scale= (const float*)d_in[19];
    const float* prior_scale= (const float*)d_in[20];
    const float* query_basis= (const float*)d_in[21];
    const float* routing_bias=(const float*)d_in[22];

    float* out        = (float*)d_out;
    float* out_hidden = out;
    float* out_emb    = out + (size_t)BB * CC * TT * KK;

    float *emb0, *kbuf, *vbuf, *qseed, *qbuf, *scores, *att, *hidden, *hffn, *glu, *invrms, *invrms2;
    cudaGetSymbolAddress((void**)&emb0,    g_emb0);
    cudaGetSymbolAddress((void**)&kbuf,    g_kbuf);
    cudaGetSymbolAddress((void**)&vbuf,    g_vbuf);
    cudaGetSymbolAddress((void**)&qseed,   g_qseed);
    cudaGetSymbolAddress((void**)&qbuf,    g_qbuf);
    cudaGetSymbolAddress((void**)&scores,  g_scores);
    cudaGetSymbolAddress((void**)&att,     g_att);
    cudaGetSymbolAddress((void**)&hidden,  g_hidden);
    cudaGetSymbolAddress((void**)&hffn,    g_hffn);
    cudaGetSymbolAddress((void**)&glu,     g_glu);
    cudaGetSymbolAddress((void**)&invrms,  g_invrms);
    cudaGetSymbolAddress((void**)&invrms2, g_invrms2);

    const int NBT  = BB * TT;         // 800
    const int NF   = TT * FF;         // 102400
    const int NK   = TT * KK;         // 12800

    // 1. inv rms of x
    rms1_kernel<<<NBT, FF>>>(x);
    // 2. pre pw: emb0 = W @ (rmsnorm(x))   [tf32 tensor cores]
    gemm_tf32<<<dim3(NF/128, CC/128, BB), 256>>>(pre_pw_w, pre_pw_b, x, emb0,
                                                 invrms, pre_norm_w, nullptr, CC, CC, NF);
    // 3. depthwise conv + SiLU -> emb (directly into d_out)
    dwconv_kernel<<<BB*CC*TT, FF>>>(pre_dw_w, pre_dw_b, out_emb);
    // 4/5. k, v projections
    gemm_tf32<<<dim3(NF/128, CC/128, BB), 256>>>(k_w, k_b, out_emb, kbuf,
                                                 nullptr, nullptr, nullptr, CC, CC, NF);
    gemm_tf32<<<dim3(NF/128, CC/128, BB), 256>>>(v_w, v_b, out_emb, vbuf,
                                                 nullptr, nullptr, nullptr, CC, CC, NF);
    // 6. query seed: basis pooling
    gemm_abT_kernel<<<NBT, 256>>>(out_emb, query_basis, 0, qseed);
    // 7. q projection
    gemm_tf32<<<dim3(NK/128, CC/128, BB), 256>>>(q_w, q_b, qseed, qbuf,
                                                 nullptr, nullptr, nullptr, CC, CC, NK);
    // 8. scores
    scores_kernel<<<NBT, 256>>>(qbuf, kbuf, routing_bias, score_scale, prior_scale, scores);
    // 9. softmax over F (in place)
    softmax_kernel<<<NBT * KK, FF>>>(scores);
    // 10. attended
    gemm_abT_kernel<<<NBT, 256>>>(vbuf, scores, (long)KK * FF, att);
    // 11. out projection -> hidden
    gemm_tf32<<<dim3(NK/128, CC/128, BB), 256>>>(out_w, out_b, att, hidden,
                                                 nullptr, nullptr, nullptr, CC, CC, NK);
    // 12. inv rms of hidden
    rms2_kernel<<<NBT/8, dim3(KK, 8)>>>();
    // 13. ffn_in (2C outputs) on rmsnorm(hidden)
    gemm_tf32<<<dim3(NK/128, 2*CC/128, BB), 256>>>(ffn_in_w, ffn_in_b, hidden, hffn,
                                                   invrms2, ffn_norm_w, nullptr, CC, 2*CC, NK);
    // 14. GLU
    glu_kernel<<<(BB*CC*TT*KK)/256, 256>>>();
    // 15. ffn_out + residual -> final hidden into d_out
    gemm_tf32<<<dim3(NK/128, CC/128, BB), 256>>>(ffn_out_w, ffn_out_b, glu, out_hidden,
                                                 nullptr, nullptr, hidden, CC, CC, NK);
}

// round 3
// speedup vs baseline: 4.2225x; 1.5667x over previous
#include <cuda_runtime.h>
#include <math.h>

#define BB 2
#define CC 256
#define TT 400
#define FF 256
#define KK 32
#define EPSV 1e-6f

typedef unsigned long long ull;

// ---------------- scratch (static device globals; allocation-free) ----------
__device__ float g_invrms [BB*TT*FF];
__device__ float g_emb0   [(size_t)BB*CC*TT*FF];
__device__ float g_qseed  [(size_t)BB*CC*TT*KK];
__device__ float g_q2     [(size_t)BB*CC*TT*KK];
__device__ float g_weights[(size_t)BB*TT*KK*FF];
__device__ float g_pooled [(size_t)BB*CC*TT*KK];
__device__ float g_hidden [(size_t)BB*CC*TT*KK];
__device__ float g_hffn   [(size_t)BB*2*CC*TT*KK];
__device__ float g_glu    [(size_t)BB*CC*TT*KK];
__device__ float g_invrms2[BB*TT*KK];
__device__ float g_P      [CC*CC];     // P[j][i] = sum_o kw[o,j] qw[o,i]
__device__ float g_OV     [CC*CC];     // OV[o][j] = sum_v ow[o,v] vw[v,j]
__device__ float g_u      [CC];        // u[j] = sum_o qb[o] kw[o,j]
__device__ float g_w2     [CC];        // w2[i] = sum_o qw[o,i] kb[o]
__device__ float g_bias2  [CC];        // Ow vb + ob
__device__ float g_colt   [BB*TT*KK];  // sum_i w2[i] qseed[i,k] + s0
__device__ float g_misc   [4];

// ---------------- helpers ----------------------------------------------------
__device__ __forceinline__ unsigned f2tf32(float f) {
    unsigned r;
    asm("cvt.rna.tf32.f32 %0, %1;" : "=r"(r) : "f"(f));
    return r;
}
__device__ __forceinline__ void mma_tf32(float* c, const unsigned* a, const unsigned* b) {
    asm volatile(
        "mma.sync.aligned.m16n8k8.row.col.f32.tf32.tf32.f32 "
        "{%0,%1,%2,%3}, {%4,%5,%6,%7}, {%8,%9}, {%0,%1,%2,%3};\n"
        : "+f"(c[0]), "+f"(c[1]), "+f"(c[2]), "+f"(c[3])
        : "r"(a[0]), "r"(a[1]), "r"(a[2]), "r"(a[3]), "r"(b[0]), "r"(b[1]));
}
__device__ __forceinline__ ull pack2(float x, float y) {
    ull r;
    asm("mov.b64 %0, {%1,%2};" : "=l"(r) : "f"(x), "f"(y));
    return r;
}
__device__ __forceinline__ void unpack2(ull v, float& x, float& y) {
    asm("mov.b64 {%0,%1}, %2;" : "=f"(x), "=f"(y) : "l"(v));
}
__device__ __forceinline__ ull fma2(ull a, ull b, ull c) {
    ull d;
    asm("fma.rn.f32x2 %0, %1, %2, %3;" : "=l"(d) : "l"(a), "l"(b), "l"(c));
    return d;
}

// ---------------- batched pointwise GEMM on tensor cores ---------------------
__global__ void __launch_bounds__(256, 2)
gemm_tf32(const float* __restrict__ W, const float* __restrict__ bias,
          const float* __restrict__ X, float* __restrict__ Y,
          const float* __restrict__ colscale, const float* __restrict__ rowscale,
          const float* __restrict__ addsrc,
          int K, int Cout, int Ntot)
{
    const int BM = 128, BN = 128, BK = 32;
    __shared__ unsigned Ws[BM][BK + 4];
    __shared__ unsigned Xs[BK][BN + 4];

    int b  = blockIdx.z;
    int n0 = blockIdx.x * BN;
    int o0 = blockIdx.y * BM;
    const float* Xb = X + (size_t)b * K * Ntot;
    float*       Yb = Y + (size_t)b * Cout * Ntot;
    const float* As = addsrc ? addsrc + (size_t)b * Cout * Ntot : nullptr;
    const float* cs = colscale ? colscale + (size_t)b * Ntot : nullptr;

    int tid  = threadIdx.x;
    int warp = tid >> 5, lane = tid & 31;
    int wm = warp & 3, wn = warp >> 2;
    int group = lane >> 2, tid4 = lane & 3;

    float acc[2][8][4];
    #pragma unroll
    for (int mt = 0; mt < 2; mt++)
        #pragma unroll
        for (int nt = 0; nt < 8; nt++)
            #pragma unroll
            for (int r = 0; r < 4; r++) acc[mt][nt][r] = 0.f;

    for (int k0 = 0; k0 < K; k0 += BK) {
        #pragma unroll
        for (int i = 0; i < 4; i++) {
            int e = i * 256 + tid;
            int m = e >> 3;
            int kk4 = (e & 7) * 4;
            float4 v = *(const float4*)(W + (size_t)(o0 + m) * K + k0 + kk4);
            Ws[m][kk4 + 0] = f2tf32(v.x);
            Ws[m][kk4 + 1] = f2tf32(v.y);
            Ws[m][kk4 + 2] = f2tf32(v.z);
            Ws[m][kk4 + 3] = f2tf32(v.w);
        }
        #pragma unroll
        for (int i = 0; i < 4; i++) {
            int e = i * 256 + tid;
            int kk = e >> 5;
            int nn4 = (e & 31) * 4;
            float4 v = *(const float4*)(Xb + (size_t)(k0 + kk) * Ntot + n0 + nn4);
            if (cs) {
                float4 s = *(const float4*)(cs + n0 + nn4);
                v.x *= s.x; v.y *= s.y; v.z *= s.z; v.w *= s.w;
            }
            if (rowscale) {
                float rs = rowscale[k0 + kk];
                v.x *= rs; v.y *= rs; v.z *= rs; v.w *= rs;
            }
            Xs[kk][nn4 + 0] = f2tf32(v.x);
            Xs[kk][nn4 + 1] = f2tf32(v.y);
            Xs[kk][nn4 + 2] = f2tf32(v.z);
            Xs[kk][nn4 + 3] = f2tf32(v.w);
        }
        __syncthreads();

        #pragma unroll
        for (int ks = 0; ks < BK; ks += 8) {
            unsigned a[2][4], bf[8][2];
            #pragma unroll
            for (int mt = 0; mt < 2; mt++) {
                int mr = wm * 32 + mt * 16 + group;
                a[mt][0] = Ws[mr    ][ks + tid4];
                a[mt][1] = Ws[mr + 8][ks + tid4];
                a[mt][2] = Ws[mr    ][ks + tid4 + 4];
                a[mt][3] = Ws[mr + 8][ks + tid4 + 4];
            }
            #pragma unroll
            for (int nt = 0; nt < 8; nt++) {
                int nc = wn * 64 + nt * 8 + group;
                bf[nt][0] = Xs[ks + tid4    ][nc];
                bf[nt][1] = Xs[ks + tid4 + 4][nc];
            }
            #pragma unroll
            for (int mt = 0; mt < 2; mt++)
                #pragma unroll
                for (int nt = 0; nt < 8; nt++)
                    mma_tf32(acc[mt][nt], a[mt], bf[nt]);
        }
        __syncthreads();
    }

    #pragma unroll
    for (int mt = 0; mt < 2; mt++) {
        int row = o0 + wm * 32 + mt * 16 + group;
        float bv0 = bias ? bias[row]     : 0.f;
        float bv8 = bias ? bias[row + 8] : 0.f;
        #pragma unroll
        for (int nt = 0; nt < 8; nt++) {
            int col = n0 + wn * 64 + nt * 8 + tid4 * 2;
            size_t i0 = (size_t)row * Ntot + col;
            size_t i8 = (size_t)(row + 8) * Ntot + col;
            float2 v0 = make_float2(acc[mt][nt][0] + bv0, acc[mt][nt][1] + bv0);
            float2 v8 = make_float2(acc[mt][nt][2] + bv8, acc[mt][nt][3] + bv8);
            if (As) {
                float2 a0 = *(const float2*)(As + i0);
                float2 a8 = *(const float2*)(As + i8);
                v0.x += a0.x; v0.y += a0.y;
                v8.x += a8.x; v8.y += a8.y;
            }
            *(float2*)(Yb + i0) = v0;
            *(float2*)(Yb + i8) = v8;
        }
    }
}

// ---------------- small fp32 precompute GEMMs --------------------------------
// tn: C[m][n] = sum_r A[r*C+m] * B[r*C+n]
__global__ void tn_gemm256(const float* __restrict__ A, const float* __restrict__ B,
                           float* __restrict__ Cm) {
    __shared__ float As[32][33], Bs[32][33];
    int m0 = blockIdx.y * 32, n0 = blockIdx.x * 32;
    int tx = threadIdx.x, ty = threadIdx.y;
    int tid = ty * 16 + tx;
    float acc[2][2] = {{0.f,0.f},{0.f,0.f}};
    for (int r0 = 0; r0 < CC; r0 += 32) {
        #pragma unroll
        for (int i = 0; i < 4; i++) {
            int e = i * 256 + tid;
            int r = e >> 5, c = e & 31;
            As[r][c] = A[(size_t)(r0 + r) * CC + m0 + c];
            Bs[r][c] = B[(size_t)(r0 + r) * CC + n0 + c];
        }
        __syncthreads();
        #pragma unroll
        for (int r = 0; r < 32; r++) {
            float a0 = As[r][ty*2], a1 = As[r][ty*2+1];
            float b0 = Bs[r][tx*2], b1 = Bs[r][tx*2+1];
            acc[0][0] += a0*b0; acc[0][1] += a0*b1;
            acc[1][0] += a1*b0; acc[1][1] += a1*b1;
        }
        __syncthreads();
    }
    #pragma unroll
    for (int i = 0; i < 2; i++)
        #pragma unroll
        for (int j = 0; j < 2; j++)
            Cm[(size_t)(m0 + ty*2 + i) * CC + n0 + tx*2 + j] = acc[i][j];
}

// nn: C[m][n] = sum_r A[m*C+r] * B[r*C+n]
__global__ void nn_gemm256(const float* __restrict__ A, const float* __restrict__ B,
                           float* __restrict__ Cm) {
    __shared__ float As[32][33], Bs[32][33];
    int m0 = blockIdx.y * 32, n0 = blockIdx.x * 32;
    int tx = threadIdx.x, ty = threadIdx.y;
    int tid = ty * 16 + tx;
    float acc[2][2] = {{0.f,0.f},{0.f,0.f}};
    for (int r0 = 0; r0 < CC; r0 += 32) {
        #pragma unroll
        for (int i = 0; i < 4; i++) {
            int e = i * 256 + tid;
            int a = e >> 5, c = e & 31;
            As[a][c] = A[(size_t)(m0 + a) * CC + r0 + c];
            Bs[a][c] = B[(size_t)(r0 + a) * CC + n0 + c];
        }
        __syncthreads();
        #pragma unroll
        for (int r = 0; r < 32; r++) {
            float a0 = As[ty*2][r], a1 = As[ty*2+1][r];
            float b0 = Bs[r][tx*2], b1 = Bs[r][tx*2+1];
            acc[0][0] += a0*b0; acc[0][1] += a0*b1;
            acc[1][0] += a1*b0; acc[1][1] += a1*b1;
        }
        __syncthreads();
    }
    #pragma unroll
    for (int i = 0; i < 2; i++)
        #pragma unroll
        for (int j = 0; j < 2; j++)
            Cm[(size_t)(m0 + ty*2 + i) * CC + n0 + tx*2 + j] = acc[i][j];
}

// vectors: u, w2, bias2, s0
__global__ void vec_pre_kernel(const float* __restrict__ qw, const float* __restrict__ qb,
                               const float* __restrict__ kw, const float* __restrict__ kb,
                               const float* __restrict__ ow, const float* __restrict__ ob,
                               const float* __restrict__ vb) {
    int j = threadIdx.x;
    float su = 0.f, sw = 0.f, sb = 0.f;
    for (int o = 0; o < CC; o++) {
        su += qb[o] * kw[(size_t)o * CC + j];
        sw += qw[(size_t)o * CC + j] * kb[o];
        sb += ow[(size_t)j * CC + o] * vb[o];
    }
    g_u[j] = su;
    g_w2[j] = sw;
    g_bias2[j] = sb + ob[j];
    if (j == 0) {
        float s0 = 0.f;
        for (int o = 0; o < CC; o++) s0 += qb[o] * kb[o];
        g_misc[0] = s0;
    }
}

// colt[bt][k] = sum_i w2[i] * qseed[b,i,t,k] + s0
__global__ void colt_kernel(const float* __restrict__ qseed) {
    int bt = blockIdx.x;
    int k = threadIdx.x;
    int b = bt / TT, t = bt % TT;
    size_t base = ((size_t)b * CC * TT + t) * KK + k;
    float s = 0.f;
    #pragma unroll 4
    for (int i = 0; i < CC; i++)
        s += g_w2[i] * qseed[base + (size_t)i * TT * KK];
    g_colt[bt * KK + k] = s + g_misc[0];
}

// ---------------- inv rms of x over channel dim ------------------------------
__global__ void rms1_kernel(const float* __restrict__ x) {
    int bt = blockIdx.x;
    int f  = threadIdx.x;
    int b = bt / TT, t = bt % TT;
    size_t base = ((size_t)b * CC * TT + t) * FF + f;
    float s = 0.f;
    #pragma unroll 4
    for (int c = 0; c < CC; c++) {
        float v = x[base + (size_t)c * TT * FF];
        s += v * v;
    }
    g_invrms[bt * FF + f] = rsqrtf(s * (1.f / CC) + EPSV);
}

// ---------------- depthwise 3x3 causal conv + SiLU, 8 t per block ------------
#define TB 8
__global__ void dwconv8_kernel(const float* __restrict__ dww, const float* __restrict__ dwb,
                               float* __restrict__ emb) {
    int nblk = TT / TB;
    long idx = blockIdx.x;
    int tb = (int)(idx % nblk);
    long bc = idx / nblk;
    int c = (int)(bc % CC);
    int t0 = tb * TB;
    int f = threadIdx.x;
    __shared__ float rows[TB + 2][FF + 2];
    size_t chbase = (size_t)bc * TT * FF;
    #pragma unroll
    for (int r = 0; r < TB + 2; r++) {
        int tt = t0 - 2 + r;
        rows[r][f + 1] = (tt >= 0) ? g_emb0[chbase + (size_t)tt * FF + f] : 0.f;
        if (f == 0) { rows[r][0] = 0.f; rows[r][FF + 1] = 0.f; }
    }
    __syncthreads();
    float w[9];
    #pragma unroll
    for (int i = 0; i < 9; i++) w[i] = dww[c * 9 + i];
    float bv = dwb[c];
    #pragma unroll
    for (int r = 0; r < TB; r++) {
        float s = bv;
        #pragma unroll
        for (int dt = 0; dt < 3; dt++)
            #pragma unroll
            for (int df = 0; df < 3; df++)
                s += w[dt * 3 + df] * rows[r + dt][f + df];
        s = s / (1.f + __expf(-s));
        emb[chbase + (size_t)(t0 + r) * FF + f] = s;
    }
}

// ---------------- per-frame A(CxF) * B(KxF)^T -> Y(CxK), f32x2 ---------------
__global__ void __launch_bounds__(256)
abT2_kernel(const float* __restrict__ A, const float* __restrict__ Bm,
            long bStride, float* __restrict__ Y) {
    __shared__ float As[256][33];
    __shared__ __align__(16) float Bs[32][36];
    int bt = blockIdx.x;
    int b = bt / TT, t = bt % TT;
    size_t aframe = ((size_t)b * CC * TT + t) * FF;
    size_t yframe = ((size_t)b * CC * TT + t) * KK;
    const float* Bp = Bm + (size_t)bt * bStride;
    int tid = threadIdx.x;

    ull acc2[16];
    #pragma unroll
    for (int j = 0; j < 16; j++) acc2[j] = pack2(0.f, 0.f);

    for (int fc = 0; fc < FF; fc += 32) {
        #pragma unroll
        for (int i = 0; i < 32; i++) {
            int e = i * 256 + tid;
            int c = e >> 5, ff = e & 31;
            As[c][ff] = A[aframe + (size_t)c * TT * FF + fc + ff];
        }
        #pragma unroll
        for (int i = 0; i < 4; i++) {
            int e = i * 256 + tid;
            int k = e >> 5, ff = e & 31;
            Bs[ff][k] = Bp[(size_t)k * FF + fc + ff];
        }
        __syncthreads();
        #pragma unroll
        for (int ff = 0; ff < 32; ff++) {
            float av = As[tid][ff];
            ull av2 = pack2(av, av);
            const ulonglong2* brow = (const ulonglong2*)&Bs[ff][0];
            #pragma unroll
            for (int j = 0; j < 8; j++) {
                ulonglong2 bv = brow[j];
                acc2[2*j]   = fma2(av2, bv.x, acc2[2*j]);
                acc2[2*j+1] = fma2(av2, bv.y, acc2[2*j+1]);
            }
        }
        __syncthreads();
    }
    // stage via As for coalesced store
    #pragma unroll
    for (int j = 0; j < 16; j++) {
        float lo, hi;
        unpack2(acc2[j], lo, hi);
        As[tid][2*j] = lo;
        As[tid][2*j+1] = hi;
    }
    __syncthreads();
    #pragma unroll
    for (int i = 0; i < 32; i++) {
        int e = i * 256 + tid;
        int c = e >> 5, k = e & 31;
        Y[yframe + (size_t)c * TT * KK + k] = As[c][k];
    }
}

// ---------------- fused scores + softmax, f32x2 ------------------------------
// scores[k,f] = ss*( sum_c q2[c,k]*emb[c,f] + rowterm[f] + colt[k] ) + rb[k,f]*ps
// then softmax over f, weights written to g_weights[bt][k][f].
__global__ void __launch_bounds__(256)
scores_softmax_kernel(const float* __restrict__ Q2, const float* __restrict__ emb,
                      const float* __restrict__ rb,
                      const float* __restrict__ ssp, const float* __restrict__ psp,
                      float* __restrict__ Wout) {
    // union buffer: qs (32KB) during mainloop, Sm (33.8KB) afterwards
    __shared__ __align__(16) char sbuf[32 * 264 * 4];
    __shared__ float us[256];
    __shared__ float colts[32];
    ulonglong2* qs2v = (ulonglong2*)sbuf;        // [256][8]
    float* Sm = (float*)sbuf;                    // [32][264]

    int bt = blockIdx.x;
    int b = bt / TT, t = bt % TT;
    size_t qframe = ((size_t)b * CC * TT + t) * KK;
    size_t eframe = ((size_t)b * CC * TT + t) * FF;
    int tid = threadIdx.x;
    int lane = tid & 31, warp = tid >> 5;

    // load q2 frame [c][k] as ull pairs
    #pragma unroll
    for (int i = 0; i < 8; i++) {
        int e = i * 256 + tid;          // float4 slot: c = e>>3, j = e&7
        int c = e >> 3, j = e & 7;
        float4 v = *(const float4*)(Q2 + qframe + (size_t)c * TT * KK + j * 4);
        ulonglong2 p;
        p.x = pack2(v.x, v.y);
        p.y = pack2(v.z, v.w);
        qs2v[c * 8 + j] = p;
    }
    us[tid] = g_u[tid];
    if (tid < 32) colts[tid] = g_colt[bt * KK + tid];
    __syncthreads();

    int f = tid;
    float acc_u = 0.f;
    ull acc2[16];
    #pragma unroll
    for (int j = 0; j < 16; j++) acc2[j] = pack2(0.f, 0.f);

    #pragma unroll 4
    for (int c = 0; c < CC; c++) {
        float kv = emb[eframe + (size_t)c * TT * FF + f];
        acc_u = fmaf(us[c], kv, acc_u);
        ull kv2 = pack2(kv, kv);
        const ulonglong2* qrow = &qs2v[c * 8];
        #pragma unroll
        for (int j = 0; j < 8; j++) {
            ulonglong2 qv = qrow[j];
            acc2[2*j]   = fma2(qv.x, kv2, acc2[2*j]);
            acc2[2*j+1] = fma2(qv.y, kv2, acc2[2*j+1]);
        }
    }
    float ss = *ssp, ps = *psp;
    float vals[32];
    #pragma unroll
    for (int j = 0; j < 16; j++) unpack2(acc2[j], vals[2*j], vals[2*j+1]);
    __syncthreads();   // qs buffer dead, reuse as Sm
    #pragma unroll
    for (int k = 0; k < 32; k++) {
        float v = ss * (vals[k] + acc_u + colts[k]) + rb[k * FF + f] * ps;
        Sm[k * 264 + f] = v;
    }
    __syncthreads();

    // softmax: each warp handles 4 rows
    #pragma unroll
    for (int rr = 0; rr < 4; rr++) {
        int k = warp * 4 + rr;
        float v[8];
        float m = -1e30f;
        #pragma unroll
        for (int i = 0; i < 8; i++) {
            v[i] = Sm[k * 264 + lane + 32 * i];
            m = fmaxf(m, v[i]);
        }
        #pragma unroll
        for (int o = 16; o; o >>= 1) m = fmaxf(m, __shfl_xor_sync(0xffffffffu, m, o));
        float s = 0.f;
        #pragma unroll
        for (int i = 0; i < 8; i++) { v[i] = __expf(v[i] - m); s += v[i]; }
        #pragma unroll
        for (int o = 16; o; o >>= 1) s += __shfl_xor_sync(0xffffffffu, s, o);
        float inv = 1.f / s;
        #pragma unroll
        for (int i = 0; i < 8; i++)
            Wout[(size_t)bt * KK * FF + k * FF + lane + 32 * i] = v[i] * inv;
    }
}

// ---------------- inv rms of hidden over channels ----------------------------
__global__ void rms2_kernel() {
    int k = threadIdx.x;
    int bt = blockIdx.x * blockDim.y + threadIdx.y;
    int b = bt / TT, t = bt % TT;
    size_t base = ((size_t)b * CC * TT + t) * KK + k;
    float s = 0.f;
    #pragma unroll 4
    for (int c = 0; c < CC; c++) {
        float v = g_hidden[base + (size_t)c * TT * KK];
        s += v * v;
    }
    g_invrms2[bt * KK + k] = rsqrtf(s * (1.f / CC) + EPSV);
}

// ---------------- GLU: a * silu(b) --------------------------------------------
__global__ void glu_kernel() {
    long i = (long)blockIdx.x * blockDim.x + threadIdx.x;
    const long CTK = (long)CC * TT * KK;
    long b = i / CTK, r = i % CTK;
    float a  = g_hffn[b * 2 * CTK + r];
    float bb = g_hffn[b * 2 * CTK + CTK + r];
    g_glu[i] = a * (bb / (1.f + __expf(-bb)));
}

// ---------------- host launcher ------------------------------------------------
extern "C" void kernel_launch(void* const* d_in, const int* in_sizes, int n_in,
                              void* d_out, int out_size) {
    const float* x          = (const float*)d_in[0];
    const float* pre_norm_w = (const float*)d_in[1];
    const float* pre_pw_w   = (const float*)d_in[2];
    const float* pre_pw_b   = (const float*)d_in[3];
    const float* pre_dw_w   = (const float*)d_in[4];
    const float* pre_dw_b   = (const float*)d_in[5];
    const float* q_w        = (const float*)d_in[6];
    const float* q_b        = (const float*)d_in[7];
    const float* k_w        = (const float*)d_in[8];
    const float* k_b        = (const float*)d_in[9];
    const float* v_w        = (const float*)d_in[10];
    const float* v_b        = (const float*)d_in[11];
    const float* out_w      = (const float*)d_in[12];
    const float* out_b      = (const float*)d_in[13];
    const float* ffn_norm_w = (const float*)d_in[14];
    const float* ffn_in_w   = (const float*)d_in[15];
    const float* ffn_in_b   = (const float*)d_in[16];
    const float* ffn_out_w  = (const float*)d_in[17];
    const float* ffn_out_b  = (const float*)d_in[18];
    const float* score_scale= (const float*)d_in[19];
    const float* prior_scale= (const float*)d_in[20];
    const float* query_basis= (const float*)d_in[21];
    const float* routing_bias=(const float*)d_in[22];

    float* out        = (float*)d_out;
    float* out_hidden = out;
    float* out_emb    = out + (size_t)BB * CC * TT * KK;

    float *emb0, *qseed, *q2, *weights, *pooled, *hidden, *hffn, *glu;
    float *invrms, *invrms2, *P, *OV, *bias2;
    cudaGetSymbolAddress((void**)&emb0,    g_emb0);
    cudaGetSymbolAddress((void**)&qseed,   g_qseed);
    cudaGetSymbolAddress((void**)&q2,      g_q2);
    cudaGetSymbolAddress((void**)&weights, g_weights);
    cudaGetSymbolAddress((void**)&pooled,  g_pooled);
    cudaGetSymbolAddress((void**)&hidden,  g_hidden);
    cudaGetSymbolAddress((void**)&hffn,    g_hffn);
    cudaGetSymbolAddress((void**)&glu,     g_glu);
    cudaGetSymbolAddress((void**)&invrms,  g_invrms);
    cudaGetSymbolAddress((void**)&invrms2, g_invrms2);
    cudaGetSymbolAddress((void**)&P,       g_P);
    cudaGetSymbolAddress((void**)&OV,      g_OV);
    cudaGetSymbolAddress((void**)&bias2,   g_bias2);

    const int NBT  = BB * TT;         // 800
    const int NF   = TT * FF;         // 102400
    const int NK   = TT * KK;         // 12800

    // precompute (fp32): P = Kw^T Qw, OV = Ow Vw, u/w2/bias2/s0
    tn_gemm256<<<dim3(8, 8), dim3(16, 16)>>>(k_w, q_w, P);
    nn_gemm256<<<dim3(8, 8), dim3(16, 16)>>>(out_w, v_w, OV);
    vec_pre_kernel<<<1, 256>>>(q_w, q_b, k_w, k_b, out_w, out_b, v_b);

    // 1. inv rms of x
    rms1_kernel<<<NBT, FF>>>(x);
    // 2. pre pw: emb0 = W @ rmsnorm(x)
    gemm_tf32<<<dim3(NF/128, CC/128, BB), 256>>>(pre_pw_w, pre_pw_b, x, emb0,
                                                 invrms, pre_norm_w, nullptr, CC, CC, NF);
    // 3. depthwise conv + SiLU -> emb (into d_out)
    dwconv8_kernel<<<(long)BB*CC*(TT/TB), FF>>>(pre_dw_w, pre_dw_b, out_emb);
    // 4. qseed = emb @ basis^T
    abT2_kernel<<<NBT, 256>>>(out_emb, query_basis, 0, qseed);
    // 5. q2 = P @ qseed
    gemm_tf32<<<dim3(NK/128, CC/128, BB), 256>>>(P, nullptr, qseed, q2,
                                                 nullptr, nullptr, nullptr, CC, CC, NK);
    // 6. colt
    colt_kernel<<<NBT, KK>>>(qseed);
    // 7. scores + softmax -> weights
    scores_softmax_kernel<<<NBT, 256>>>(q2, out_emb, routing_bias,
                                        score_scale, prior_scale, weights);
    // 8. pooled = emb @ weights^T
    abT2_kernel<<<NBT, 256>>>(out_emb, weights, (long)KK * FF, pooled);
    // 9. hidden = OV @ pooled + bias2
    gemm_tf32<<<dim3(NK/128, CC/128, BB), 256>>>(OV, bias2, pooled, hidden,
                                                 nullptr, nullptr, nullptr, CC, CC, NK);
    // 10. inv rms of hidden
    rms2_kernel<<<NBT/8, dim3(KK, 8)>>>();
    // 11. ffn_in
    gemm_tf32<<<dim3(NK/128, 2*CC/128, BB), 256>>>(ffn_in_w, ffn_in_b, hidden, hffn,
                                                   invrms2, ffn_norm_w, nullptr, CC, 2*CC, NK);
    // 12. GLU
    glu_kernel<<<(BB*CC*TT*KK)/256, 256>>>();
    // 13. ffn_out + residual -> final hidden into d_out
    gemm_tf32<<<dim3(NK/128, CC/128, BB), 256>>>(ffn_out_w, ffn_out_b, glu, out_hidden,
                                                 nullptr, nullptr, hidden, CC, CC, NK);
}

// round 4
// speedup vs baseline: 4.3603x; 1.0326x over previous
#include <cuda_runtime.h>
#include <math.h>

#define BB 2
#define CC 256
#define TT 400
#define FF 256
#define KK 32
#define EPSV 1e-6f

typedef unsigned long long ull;

// ---------------- scratch ------------------------------------------------------
__device__ float g_invrms [BB*TT*FF];
__device__ float g_emb0   [(size_t)BB*CC*TT*FF];
__device__ float g_qseed  [(size_t)BB*CC*TT*KK];
__device__ float g_q2     [(size_t)BB*CC*TT*KK];
__device__ float g_pooled [(size_t)BB*CC*TT*KK];
__device__ float g_hidden [(size_t)BB*CC*TT*KK];
__device__ float g_hffn   [(size_t)BB*2*CC*TT*KK];
__device__ float g_glu    [(size_t)BB*CC*TT*KK];
__device__ float g_invrms2[BB*TT*KK];
__device__ float g_P      [CC*CC];
__device__ float g_OV     [CC*CC];
__device__ float g_u      [CC];
__device__ float g_w2     [CC];
__device__ float g_bias2  [CC];
__device__ float g_colt   [BB*TT*KK];
__device__ float g_misc   [4];

// ---------------- helpers ------------------------------------------------------
__device__ __forceinline__ unsigned f2tf32(float f) {
    unsigned r;
    asm("cvt.rna.tf32.f32 %0, %1;" : "=r"(r) : "f"(f));
    return r;
}
__device__ __forceinline__ void mma_tf32(float* c, const unsigned* a, const unsigned* b) {
    asm volatile(
        "mma.sync.aligned.m16n8k8.row.col.f32.tf32.tf32.f32 "
        "{%0,%1,%2,%3}, {%4,%5,%6,%7}, {%8,%9}, {%0,%1,%2,%3};\n"
        : "+f"(c[0]), "+f"(c[1]), "+f"(c[2]), "+f"(c[3])
        : "r"(a[0]), "r"(a[1]), "r"(a[2]), "r"(a[3]), "r"(b[0]), "r"(b[1]));
}
__device__ __forceinline__ ull pack2(float x, float y) {
    ull r;
    asm("mov.b64 %0, {%1,%2};" : "=l"(r) : "f"(x), "f"(y));
    return r;
}
__device__ __forceinline__ void unpack2(ull v, float& x, float& y) {
    asm("mov.b64 {%0,%1}, %2;" : "=f"(x), "=f"(y) : "l"(v));
}
__device__ __forceinline__ ull fma2(ull a, ull b, ull c) {
    ull d;
    asm("fma.rn.f32x2 %0, %1, %2, %3;" : "=l"(d) : "l"(a), "l"(b), "l"(c));
    return d;
}
__device__ __forceinline__ void cpa16(void* dst, const void* src) {
    unsigned d = (unsigned)__cvta_generic_to_shared(dst);
    asm volatile("cp.async.ca.shared.global [%0], [%1], 16;" :: "r"(d), "l"(src));
}
#define CP_COMMIT() asm volatile("cp.async.commit_group;")
#define CP_WAIT1()  asm volatile("cp.async.wait_group 1;")
#define CP_WAIT0()  asm volatile("cp.async.wait_group 0;")

// ---------------- pipelined batched pointwise GEMM (tf32 tensor cores) ---------
// Y[b,o,n] = sum_c (W[o,c]*rowscale[c]) * (X[b,c,n]*colscale[b,n]) + bias[o] (+addsrc)
__global__ void __launch_bounds__(256, 2)
gemm_tf32p(const float* __restrict__ W, const float* __restrict__ bias,
           const float* __restrict__ X, float* __restrict__ Y,
           const float* __restrict__ colscale, const float* __restrict__ rowscale,
           const float* __restrict__ addsrc,
           int K, int Cout, int Ntot)
{
    const int BM = 128, BN = 128, BK = 16;
    __shared__ float Wf[2][BM][20];
    __shared__ float Xf[2][BK][132];
    __shared__ float rsAll[256];
    __shared__ float csAll[BN];

    int b  = blockIdx.z;
    int n0 = blockIdx.x * BN;
    int o0 = blockIdx.y * BM;
    const float* Xb = X + (size_t)b * K * Ntot;
    float*       Yb = Y + (size_t)b * Cout * Ntot;
    const float* As = addsrc ? addsrc + (size_t)b * Cout * Ntot : nullptr;

    int tid  = threadIdx.x;
    int warp = tid >> 5, lane = tid & 31;
    int wm = warp & 3, wn = warp >> 2;
    int group = lane >> 2, tid4 = lane & 3;
    bool hasRS = (rowscale != nullptr);
    bool hasCS = (colscale != nullptr);

    if (hasRS) rsAll[tid] = rowscale[tid];               // K == 256 always
    if (hasCS && tid < BN) csAll[tid] = colscale[(size_t)b * Ntot + n0 + tid];

    // per-thread load slots
    int wm_ld = tid >> 2;            // W: slot = i*256+tid -> m = slot>>2
    int wk4   = (tid & 3) * 4;
    int xk_ld = tid >> 5;            // X: kk = slot>>5
    int xn4   = (tid & 31) * 4;

    float acc[2][8][4];
    #pragma unroll
    for (int mt = 0; mt < 2; mt++)
        #pragma unroll
        for (int nt = 0; nt < 8; nt++)
            #pragma unroll
            for (int r = 0; r < 4; r++) acc[mt][nt][r] = 0.f;

    const int ntiles = K / BK;   // 16

    // prologue: tile 0 into buf 0
    {
        int k0 = 0;
        #pragma unroll
        for (int i = 0; i < 2; i++) {
            int m = i * 64 + wm_ld;
            cpa16(&Wf[0][m][wk4], W + (size_t)(o0 + m) * K + k0 + wk4);
        }
        #pragma unroll
        for (int i = 0; i < 2; i++) {
            int kk = i * 8 + xk_ld;
            cpa16(&Xf[0][kk][xn4], Xb + (size_t)(k0 + kk) * Ntot + n0 + xn4);
        }
        CP_COMMIT();
    }

    for (int kt = 0; kt < ntiles; kt++) {
        int buf = kt & 1;
        if (kt + 1 < ntiles) {
            int k0n = (kt + 1) * BK;
            int nb = buf ^ 1;
            #pragma unroll
            for (int i = 0; i < 2; i++) {
                int m = i * 64 + wm_ld;
                cpa16(&Wf[nb][m][wk4], W + (size_t)(o0 + m) * K + k0n + wk4);
            }
            #pragma unroll
            for (int i = 0; i < 2; i++) {
                int kk = i * 8 + xk_ld;
                cpa16(&Xf[nb][kk][xn4], Xb + (size_t)(k0n + kk) * Ntot + n0 + xn4);
            }
            CP_COMMIT();
            CP_WAIT1();
        } else {
            CP_WAIT0();
        }
        __syncthreads();

        int k0 = kt * BK;
        #pragma unroll
        for (int ks = 0; ks < BK; ks += 8) {
            float r0 = hasRS ? rsAll[k0 + ks + tid4]     : 1.f;
            float r1 = hasRS ? rsAll[k0 + ks + tid4 + 4] : 1.f;
            unsigned a[2][4], bf[8][2];
            #pragma unroll
            for (int mt = 0; mt < 2; mt++) {
                int mr = wm * 32 + mt * 16 + group;
                a[mt][0] = f2tf32(Wf[buf][mr    ][ks + tid4]     * r0);
                a[mt][1] = f2tf32(Wf[buf][mr + 8][ks + tid4]     * r0);
                a[mt][2] = f2tf32(Wf[buf][mr    ][ks + tid4 + 4] * r1);
                a[mt][3] = f2tf32(Wf[buf][mr + 8][ks + tid4 + 4] * r1);
            }
            #pragma unroll
            for (int nt = 0; nt < 8; nt++) {
                int nc = wn * 64 + nt * 8 + group;
                float cv = hasCS ? csAll[nc] : 1.f;
                bf[nt][0] = f2tf32(Xf[buf][ks + tid4    ][nc] * cv);
                bf[nt][1] = f2tf32(Xf[buf][ks + tid4 + 4][nc] * cv);
            }
            #pragma unroll
            for (int mt = 0; mt < 2; mt++)
                #pragma unroll
                for (int nt = 0; nt < 8; nt++)
                    mma_tf32(acc[mt][nt], a[mt], bf[nt]);
        }
        __syncthreads();
    }

    #pragma unroll
    for (int mt = 0; mt < 2; mt++) {
        int row = o0 + wm * 32 + mt * 16 + group;
        float bv0 = bias ? bias[row]     : 0.f;
        float bv8 = bias ? bias[row + 8] : 0.f;
        #pragma unroll
        for (int nt = 0; nt < 8; nt++) {
            int col = n0 + wn * 64 + nt * 8 + tid4 * 2;
            size_t i0 = (size_t)row * Ntot + col;
            size_t i8 = (size_t)(row + 8) * Ntot + col;
            float2 v0 = make_float2(acc[mt][nt][0] + bv0, acc[mt][nt][1] + bv0);
            float2 v8 = make_float2(acc[mt][nt][2] + bv8, acc[mt][nt][3] + bv8);
            if (As) {
                float2 a0 = *(const float2*)(As + i0);
                float2 a8 = *(const float2*)(As + i8);
                v0.x += a0.x; v0.y += a0.y;
                v8.x += a8.x; v8.y += a8.y;
            }
            *(float2*)(Yb + i0) = v0;
            *(float2*)(Yb + i8) = v8;
        }
    }
}

// ---------------- small fp32 precompute GEMMs ----------------------------------
__global__ void tn_gemm256(const float* __restrict__ A, const float* __restrict__ B,
                           float* __restrict__ Cm) {
    __shared__ float As[32][33], Bs[32][33];
    int m0 = blockIdx.y * 32, n0 = blockIdx.x * 32;
    int tx = threadIdx.x, ty = threadIdx.y;
    int tid = ty * 16 + tx;
    float acc[2][2] = {{0.f,0.f},{0.f,0.f}};
    for (int r0 = 0; r0 < CC; r0 += 32) {
        #pragma unroll
        for (int i = 0; i < 4; i++) {
            int e = i * 256 + tid;
            int r = e >> 5, c = e & 31;
            As[r][c] = A[(size_t)(r0 + r) * CC + m0 + c];
            Bs[r][c] = B[(size_t)(r0 + r) * CC + n0 + c];
        }
        __syncthreads();
        #pragma unroll
        for (int r = 0; r < 32; r++) {
            float a0 = As[r][ty*2], a1 = As[r][ty*2+1];
            float b0 = Bs[r][tx*2], b1 = Bs[r][tx*2+1];
            acc[0][0] += a0*b0; acc[0][1] += a0*b1;
            acc[1][0] += a1*b0; acc[1][1] += a1*b1;
        }
        __syncthreads();
    }
    #pragma unroll
    for (int i = 0; i < 2; i++)
        #pragma unroll
        for (int j = 0; j < 2; j++)
            Cm[(size_t)(m0 + ty*2 + i) * CC + n0 + tx*2 + j] = acc[i][j];
}

__global__ void nn_gemm256(const float* __restrict__ A, const float* __restrict__ B,
                           float* __restrict__ Cm) {
    __shared__ float As[32][33], Bs[32][33];
    int m0 = blockIdx.y * 32, n0 = blockIdx.x * 32;
    int tx = threadIdx.x, ty = threadIdx.y;
    int tid = ty * 16 + tx;
    float acc[2][2] = {{0.f,0.f},{0.f,0.f}};
    for (int r0 = 0; r0 < CC; r0 += 32) {
        #pragma unroll
        for (int i = 0; i < 4; i++) {
            int e = i * 256 + tid;
            int a = e >> 5, c = e & 31;
            As[a][c] = A[(size_t)(m0 + a) * CC + r0 + c];
            Bs[a][c] = B[(size_t)(r0 + a) * CC + n0 + c];
        }
        __syncthreads();
        #pragma unroll
        for (int r = 0; r < 32; r++) {
            float a0 = As[ty*2][r], a1 = As[ty*2+1][r];
            float b0 = Bs[r][tx*2], b1 = Bs[r][tx*2+1];
            acc[0][0] += a0*b0; acc[0][1] += a0*b1;
            acc[1][0] += a1*b0; acc[1][1] += a1*b1;
        }
        __syncthreads();
    }
    #pragma unroll
    for (int i = 0; i < 2; i++)
        #pragma unroll
        for (int j = 0; j < 2; j++)
            Cm[(size_t)(m0 + ty*2 + i) * CC + n0 + tx*2 + j] = acc[i][j];
}

__global__ void vec_pre_kernel(const float* __restrict__ qw, const float* __restrict__ qb,
                               const float* __restrict__ kw, const float* __restrict__ kb,
                               const float* __restrict__ ow, const float* __restrict__ ob,
                               const float* __restrict__ vb) {
    int j = threadIdx.x;
    float su = 0.f, sw = 0.f, sb = 0.f;
    for (int o = 0; o < CC; o++) {
        su += qb[o] * kw[(size_t)o * CC + j];
        sw += qw[(size_t)o * CC + j] * kb[o];
        sb += ow[(size_t)j * CC + o] * vb[o];
    }
    g_u[j] = su;
    g_w2[j] = sw;
    g_bias2[j] = sb + ob[j];
    if (j == 0) {
        float s0 = 0.f;
        for (int o = 0; o < CC; o++) s0 += qb[o] * kb[o];
        g_misc[0] = s0;
    }
}

// ---------------- inv rms of x (float4, 4-way c split) -------------------------
__global__ void rms1_kernel(const float* __restrict__ x) {
    __shared__ float4 part[4][64];
    int bt = blockIdx.x;
    int b = bt / TT, t = bt % TT;
    int tid = threadIdx.x;
    int g = tid >> 6;          // c group 0..3
    int f4 = tid & 63;         // float4 index over f
    const float4* xp = (const float4*)(x + ((size_t)b * CC * TT + t) * FF);
    const size_t rstride = (size_t)TT * FF / 4;   // float4 row stride
    float4 s = make_float4(0.f, 0.f, 0.f, 0.f);
    #pragma unroll 8
    for (int c = g; c < CC; c += 4) {
        float4 v = xp[(size_t)c * rstride + f4];
        s.x += v.x * v.x; s.y += v.y * v.y; s.z += v.z * v.z; s.w += v.w * v.w;
    }
    part[g][f4] = s;
    __syncthreads();
    if (tid < 64) {
        float4 a = part[0][tid], b2 = part[1][tid], c2 = part[2][tid], d = part[3][tid];
        float4 r;
        r.x = rsqrtf((a.x + b2.x + c2.x + d.x) * (1.f / CC) + EPSV);
        r.y = rsqrtf((a.y + b2.y + c2.y + d.y) * (1.f / CC) + EPSV);
        r.z = rsqrtf((a.z + b2.z + c2.z + d.z) * (1.f / CC) + EPSV);
        r.w = rsqrtf((a.w + b2.w + c2.w + d.w) * (1.f / CC) + EPSV);
        *(float4*)(&g_invrms[bt * FF + tid * 4]) = r;
    }
}

// ---------------- depthwise 3x3 causal conv + SiLU, 8 t per block --------------
#define TB 8
__global__ void dwconv8_kernel(const float* __restrict__ dww, const float* __restrict__ dwb,
                               float* __restrict__ emb) {
    int nblk = TT / TB;
    long idx = blockIdx.x;
    int tb = (int)(idx % nblk);
    long bc = idx / nblk;
    int c = (int)(bc % CC);
    int t0 = tb * TB;
    int f = threadIdx.x;
    __shared__ float rows[TB + 2][FF + 2];
    size_t chbase = (size_t)bc * TT * FF;
    #pragma unroll
    for (int r = 0; r < TB + 2; r++) {
        int tt = t0 - 2 + r;
        rows[r][f + 1] = (tt >= 0) ? g_emb0[chbase + (size_t)tt * FF + f] : 0.f;
        if (f == 0) { rows[r][0] = 0.f; rows[r][FF + 1] = 0.f; }
    }
    __syncthreads();
    float w[9];
    #pragma unroll
    for (int i = 0; i < 9; i++) w[i] = dww[c * 9 + i];
    float bv = dwb[c];
    #pragma unroll
    for (int r = 0; r < TB; r++) {
        float s = bv;
        #pragma unroll
        for (int dt = 0; dt < 3; dt++)
            #pragma unroll
            for (int df = 0; df < 3; df++)
                s += w[dt * 3 + df] * rows[r + dt][f + df];
        s = s / (1.f + __expf(-s));
        emb[chbase + (size_t)(t0 + r) * FF + f] = s;
    }
}

// ---------------- qseed = emb @ basis^T (+ fused colt) -------------------------
__global__ void __launch_bounds__(256)
qseed_kernel(const float* __restrict__ A, const float* __restrict__ Bm,
             float* __restrict__ Y) {
    __shared__ float As[256][33];
    __shared__ __align__(16) float Bs[32][36];
    __shared__ float w2s[256];
    int bt = blockIdx.x;
    int b = bt / TT, t = bt % TT;
    size_t aframe = ((size_t)b * CC * TT + t) * FF;
    size_t yframe = ((size_t)b * CC * TT + t) * KK;
    int tid = threadIdx.x;
    w2s[tid] = g_w2[tid];

    ull acc2[16];
    #pragma unroll
    for (int j = 0; j < 16; j++) acc2[j] = pack2(0.f, 0.f);

    for (int fc = 0; fc < FF; fc += 32) {
        #pragma unroll
        for (int i = 0; i < 32; i++) {
            int e = i * 256 + tid;
            int c = e >> 5, ff = e & 31;
            As[c][ff] = A[aframe + (size_t)c * TT * FF + fc + ff];
        }
        #pragma unroll
        for (int i = 0; i < 4; i++) {
            int e = i * 256 + tid;
            int k = e >> 5, ff = e & 31;
            Bs[ff][k] = Bm[(size_t)k * FF + fc + ff];
        }
        __syncthreads();
        #pragma unroll
        for (int ff = 0; ff < 32; ff++) {
            float av = As[tid][ff];
            ull av2 = pack2(av, av);
            const ulonglong2* brow = (const ulonglong2*)&Bs[ff][0];
            #pragma unroll
            for (int j = 0; j < 8; j++) {
                ulonglong2 bv = brow[j];
                acc2[2*j]   = fma2(av2, bv.x, acc2[2*j]);
                acc2[2*j+1] = fma2(av2, bv.y, acc2[2*j+1]);
            }
        }
        __syncthreads();
    }
    #pragma unroll
    for (int j = 0; j < 16; j++) {
        float lo, hi;
        unpack2(acc2[j], lo, hi);
        As[tid][2*j] = lo;
        As[tid][2*j+1] = hi;
    }
    __syncthreads();
    #pragma unroll
    for (int i = 0; i < 32; i++) {
        int e = i * 256 + tid;
        int c = e >> 5, k = e & 31;
        Y[yframe + (size_t)c * TT * KK + k] = As[c][k];
    }
    // fused colt: colt[bt][k] = sum_c w2[c]*qseed[c][k] + s0
    if (tid < 32) {
        float s = 0.f;
        #pragma unroll 8
        for (int c = 0; c < CC; c++) s += w2s[c] * As[c][tid];
        g_colt[bt * KK + tid] = s + g_misc[0];
    }
}

// ---------------- fused scores + softmax + pooled ------------------------------
// pass1: scores[f][k] = ss*(sum_c q2[c,k]*emb[c,f] + u.emb + colt[k]) + rb[k,f]*ps
// softmax over f (per k), weights kept in smem transposed [f][k]
// pass2: pooled[c,k] = sum_f weights[f][k] * emb[c,f]
__global__ void __launch_bounds__(256)
attn_fused_kernel(const float* __restrict__ Q2, const float* __restrict__ emb,
                  const float* __restrict__ rb,
                  const float* __restrict__ ssp, const float* __restrict__ psp,
                  float* __restrict__ pooled) {
    __shared__ __align__(16) float Sf[256][36];   // union: q2-packed | scoresT | weightsT | out stage
    __shared__ float As[256][9];
    __shared__ float us[256];
    __shared__ float colts[32];

    int bt = blockIdx.x;
    int b = bt / TT, t = bt % TT;
    size_t qframe = ((size_t)b * CC * TT + t) * KK;
    size_t eframe = ((size_t)b * CC * TT + t) * FF;
    size_t yframe = qframe;
    int tid = threadIdx.x;
    int lane = tid & 31, warp = tid >> 5;

    // ---- load q2 frame packed as f32x2 pairs into Sf region
    ull* qs2 = (ull*)&Sf[0][0];   // [256][16] pairs
    #pragma unroll
    for (int i = 0; i < 8; i++) {
        int e = i * 256 + tid;
        int c = e >> 3, j = e & 7;
        float4 v = *(const float4*)(Q2 + qframe + (size_t)c * TT * KK + j * 4);
        qs2[c * 16 + j * 2]     = pack2(v.x, v.y);
        qs2[c * 16 + j * 2 + 1] = pack2(v.z, v.w);
    }
    us[tid] = g_u[tid];
    if (tid < 32) colts[tid] = g_colt[bt * KK + tid];
    __syncthreads();

    // ---- pass 1: scores accumulation (thread = f)
    int f = tid;
    float acc_u = 0.f;
    ull acc2[16];
    #pragma unroll
    for (int j = 0; j < 16; j++) acc2[j] = pack2(0.f, 0.f);
    #pragma unroll 4
    for (int c = 0; c < CC; c++) {
        float kv = emb[eframe + (size_t)c * TT * FF + f];
        acc_u = fmaf(us[c], kv, acc_u);
        ull kv2 = pack2(kv, kv);
        const ulonglong2* qrow = (const ulonglong2*)&qs2[c * 16];
        #pragma unroll
        for (int j = 0; j < 8; j++) {
            ulonglong2 qv = qrow[j];
            acc2[2*j]   = fma2(qv.x, kv2, acc2[2*j]);
            acc2[2*j+1] = fma2(qv.y, kv2, acc2[2*j+1]);
        }
    }
    float ss = *ssp, ps = *psp;
    float vals[32];
    #pragma unroll
    for (int j = 0; j < 16; j++) unpack2(acc2[j], vals[2*j], vals[2*j+1]);
    __syncthreads();   // q2 region dead -> reuse as scoresT
    #pragma unroll
    for (int k = 0; k < 32; k++)
        Sf[f][k] = ss * (vals[k] + acc_u + colts[k]) + rb[k * FF + f] * ps;
    __syncthreads();

    // ---- softmax per k (warp handles 4 rows), in place (transposed layout)
    #pragma unroll
    for (int rr = 0; rr < 4; rr++) {
        int k = warp * 4 + rr;
        float v[8];
        float m = -1e30f;
        #pragma unroll
        for (int i = 0; i < 8; i++) {
            v[i] = Sf[lane + 32 * i][k];
            m = fmaxf(m, v[i]);
        }
        #pragma unroll
        for (int o = 16; o; o >>= 1) m = fmaxf(m, __shfl_xor_sync(0xffffffffu, m, o));
        float s = 0.f;
        #pragma unroll
        for (int i = 0; i < 8; i++) { v[i] = __expf(v[i] - m); s += v[i]; }
        #pragma unroll
        for (int o = 16; o; o >>= 1) s += __shfl_xor_sync(0xffffffffu, s, o);
        float inv = 1.f / s;
        #pragma unroll
        for (int i = 0; i < 8; i++)
            Sf[lane + 32 * i][k] = v[i] * inv;
    }
    __syncthreads();

    // ---- pass 2: pooled[c][k] = sum_f Wt[f][k] * emb[c][f]  (thread = c)
    #pragma unroll
    for (int j = 0; j < 16; j++) acc2[j] = pack2(0.f, 0.f);
    for (int fc = 0; fc < FF; fc += 8) {
        #pragma unroll
        for (int i = 0; i < 8; i++) {
            int e = i * 256 + tid;
            int c = e >> 3, ff = e & 7;
            As[c][ff] = emb[eframe + (size_t)c * TT * FF + fc + ff];
        }
        __syncthreads();
        #pragma unroll
        for (int ff = 0; ff < 8; ff++) {
            float av = As[tid][ff];
            ull av2 = pack2(av, av);
            const ulonglong2* wrow = (const ulonglong2*)&Sf[fc + ff][0];
            #pragma unroll
            for (int j = 0; j < 8; j++) {
                ulonglong2 wv = wrow[j];
                acc2[2*j]   = fma2(av2, wv.x, acc2[2*j]);
                acc2[2*j+1] = fma2(av2, wv.y, acc2[2*j+1]);
            }
        }
        __syncthreads();
    }
    // stage + coalesced store (Sf dead)
    #pragma unroll
    for (int j = 0; j < 16; j++) {
        float lo, hi;
        unpack2(acc2[j], lo, hi);
        Sf[tid][2*j] = lo;
        Sf[tid][2*j+1] = hi;
    }
    __syncthreads();
    #pragma unroll
    for (int i = 0; i < 32; i++) {
        int e = i * 256 + tid;
        int c = e >> 5, k = e & 31;
        pooled[yframe + (size_t)c * TT * KK + k] = Sf[c][k];
    }
}

// ---------------- inv rms of hidden over channels ------------------------------
__global__ void rms2_kernel() {
    int k = threadIdx.x;
    int bt = blockIdx.x * blockDim.y + threadIdx.y;
    int b = bt / TT, t = bt % TT;
    size_t base = ((size_t)b * CC * TT + t) * KK + k;
    float s = 0.f;
    #pragma unroll 4
    for (int c = 0; c < CC; c++) {
        float v = g_hidden[base + (size_t)c * TT * KK];
        s += v * v;
    }
    g_invrms2[bt * KK + k] = rsqrtf(s * (1.f / CC) + EPSV);
}

// ---------------- GLU ----------------------------------------------------------
__global__ void glu_kernel() {
    long i = (long)blockIdx.x * blockDim.x + threadIdx.x;
    const long CTK = (long)CC * TT * KK;
    long b = i / CTK, r = i % CTK;
    float a  = g_hffn[b * 2 * CTK + r];
    float bb = g_hffn[b * 2 * CTK + CTK + r];
    g_glu[i] = a * (bb / (1.f + __expf(-bb)));
}

// ---------------- host launcher -------------------------------------------------
extern "C" void kernel_launch(void* const* d_in, const int* in_sizes, int n_in,
                              void* d_out, int out_size) {
    const float* x          = (const float*)d_in[0];
    const float* pre_norm_w = (const float*)d_in[1];
    const float* pre_pw_w   = (const float*)d_in[2];
    const float* pre_pw_b   = (const float*)d_in[3];
    const float* pre_dw_w   = (const float*)d_in[4];
    const float* pre_dw_b   = (const float*)d_in[5];
    const float* q_w        = (const float*)d_in[6];
    const float* q_b        = (const float*)d_in[7];
    const float* k_w        = (const float*)d_in[8];
    const float* k_b        = (const float*)d_in[9];
    const float* v_w        = (const float*)d_in[10];
    const float* v_b        = (const float*)d_in[11];
    const float* out_w      = (const float*)d_in[12];
    const float* out_b      = (const float*)d_in[13];
    const float* ffn_norm_w = (const float*)d_in[14];
    const float* ffn_in_w   = (const float*)d_in[15];
    const float* ffn_in_b   = (const float*)d_in[16];
    const float* ffn_out_w  = (const float*)d_in[17];
    const float* ffn_out_b  = (const float*)d_in[18];
    const float* score_scale= (const float*)d_in[19];
    const float* prior_scale= (const float*)d_in[20];
    const float* query_basis= (const float*)d_in[21];
    const float* routing_bias=(const float*)d_in[22];

    float* out        = (float*)d_out;
    float* out_hidden = out;
    float* out_emb    = out + (size_t)BB * CC * TT * KK;

    float *emb0, *qseed, *q2, *pooled, *hidden, *hffn, *glu;
    float *invrms, *invrms2, *P, *OV, *bias2;
    cudaGetSymbolAddress((void**)&emb0,    g_emb0);
    cudaGetSymbolAddress((void**)&qseed,   g_qseed);
    cudaGetSymbolAddress((void**)&q2,      g_q2);
    cudaGetSymbolAddress((void**)&pooled,  g_pooled);
    cudaGetSymbolAddress((void**)&hidden,  g_hidden);
    cudaGetSymbolAddress((void**)&hffn,    g_hffn);
    cudaGetSymbolAddress((void**)&glu,     g_glu);
    cudaGetSymbolAddress((void**)&invrms,  g_invrms);
    cudaGetSymbolAddress((void**)&invrms2, g_invrms2);
    cudaGetSymbolAddress((void**)&P,       g_P);
    cudaGetSymbolAddress((void**)&OV,      g_OV);
    cudaGetSymbolAddress((void**)&bias2,   g_bias2);

    const int NBT = BB * TT;       // 800
    const int NF  = TT * FF;       // 102400
    const int NK  = TT * KK;       // 12800

    // precompute
    tn_gemm256<<<dim3(8, 8), dim3(16, 16)>>>(k_w, q_w, P);
    nn_gemm256<<<dim3(8, 8), dim3(16, 16)>>>(out_w, v_w, OV);
    vec_pre_kernel<<<1, 256>>>(q_w, q_b, k_w, k_b, out_w, out_b, v_b);

    // 1. inv rms of x
    rms1_kernel<<<NBT, 256>>>(x);
    // 2. pre pw (pipelined tf32)
    gemm_tf32p<<<dim3(NF/128, CC/128, BB), 256>>>(pre_pw_w, pre_pw_b, x, emb0,
                                                  invrms, pre_norm_w, nullptr, CC, CC, NF);
    // 3. depthwise conv + SiLU -> emb (into d_out)
    dwconv8_kernel<<<(long)BB*CC*(TT/TB), FF>>>(pre_dw_w, pre_dw_b, out_emb);
    // 4. qseed (+colt fused)
    qseed_kernel<<<NBT, 256>>>(out_emb, query_basis, qseed);
    // 5. q2 = P @ qseed
    gemm_tf32p<<<dim3(NK/128, CC/128, BB), 256>>>(P, nullptr, qseed, q2,
                                                  nullptr, nullptr, nullptr, CC, CC, NK);
    // 6. fused scores + softmax + pooled
    attn_fused_kernel<<<NBT, 256>>>(q2, out_emb, routing_bias,
                                    score_scale, prior_scale, pooled);
    // 7. hidden = OV @ pooled + bias2
    gemm_tf32p<<<dim3(NK/128, CC/128, BB), 256>>>(OV, bias2, pooled, hidden,
                                                  nullptr, nullptr, nullptr, CC, CC, NK);
    // 8. inv rms of hidden
    rms2_kernel<<<NBT/8, dim3(KK, 8)>>>();
    // 9. ffn_in
    gemm_tf32p<<<dim3(NK/128, 2*CC/128, BB), 256>>>(ffn_in_w, ffn_in_b, hidden, hffn,
                                                    invrms2, ffn_norm_w, nullptr, CC, 2*CC, NK);
    // 10. GLU
    glu_kernel<<<(BB*CC*TT*KK)/256, 256>>>();
    // 11. ffn_out + residual -> d_out
    gemm_tf32p<<<dim3(NK/128, CC/128, BB), 256>>>(ffn_out_w, ffn_out_b, glu, out_hidden,
                                                  nullptr, nullptr, hidden, CC, CC, NK);
}

// round 5
// speedup vs baseline: 5.1802x; 1.1881x over previous
#include <cuda_runtime.h>
#include <cuda_fp16.h>
#include <math.h>

#define BB 2
#define CC 256
#define TT 400
#define FF 256
#define KK 32
#define EPSV 1e-6f

typedef unsigned long long ull;

// ---------------- scratch ------------------------------------------------------
__device__ float g_emb0   [(size_t)BB*CC*TT*FF];
__device__ float g_qseed  [(size_t)BB*CC*TT*KK];
__device__ float g_q2     [(size_t)BB*CC*TT*KK];
__device__ float g_pooled [(size_t)BB*CC*TT*KK];
__device__ float g_hidden [(size_t)BB*CC*TT*KK];
__device__ float g_hffn   [(size_t)BB*2*CC*TT*KK];
__device__ float g_P      [CC*CC];
__device__ float g_OV     [CC*CC];
__device__ float g_Wp     [CC*CC];
__device__ float g_Wf     [2*CC*CC];
__device__ float g_u      [CC];
__device__ float g_w2     [CC];
__device__ float g_bias2  [CC];
__device__ float g_colt   [BB*TT*KK];
__device__ float g_misc   [4];

// ---------------- helpers ------------------------------------------------------
__device__ __forceinline__ ull pack2(float x, float y) {
    ull r;
    asm("mov.b64 %0, {%1,%2};" : "=l"(r) : "f"(x), "f"(y));
    return r;
}
__device__ __forceinline__ void unpack2(ull v, float& x, float& y) {
    asm("mov.b64 {%0,%1}, %2;" : "=f"(x), "=f"(y) : "l"(v));
}
__device__ __forceinline__ ull fma2(ull a, ull b, ull c) {
    ull d;
    asm("fma.rn.f32x2 %0, %1, %2, %3;" : "=l"(d) : "l"(a), "l"(b), "l"(c));
    return d;
}
__device__ __forceinline__ unsigned sptr(const void* p) {
    return (unsigned)__cvta_generic_to_shared(p);
}
__device__ __forceinline__ void ldmx4(unsigned* a, unsigned addr) {
    asm volatile("ldmatrix.sync.aligned.m8n8.x4.shared.b16 {%0,%1,%2,%3}, [%4];"
        : "=r"(a[0]), "=r"(a[1]), "=r"(a[2]), "=r"(a[3]) : "r"(addr));
}
__device__ __forceinline__ void ldmx2t(unsigned& b0, unsigned& b1, unsigned addr) {
    asm volatile("ldmatrix.sync.aligned.m8n8.x2.trans.shared.b16 {%0,%1}, [%2];"
        : "=r"(b0), "=r"(b1) : "r"(addr));
}
__device__ __forceinline__ void mma_h(float* c, const unsigned* a, unsigned b0, unsigned b1) {
    asm volatile("mma.sync.aligned.m16n8k16.row.col.f32.f16.f16.f32 "
        "{%0,%1,%2,%3}, {%4,%5,%6,%7}, {%8,%9}, {%0,%1,%2,%3};"
        : "+f"(c[0]), "+f"(c[1]), "+f"(c[2]), "+f"(c[3])
        : "r"(a[0]), "r"(a[1]), "r"(a[2]), "r"(a[3]), "r"(b0), "r"(b1));
}

// ---------------- unified fp16 tensor-core GEMM --------------------------------
// Y[b,o,n] = epi( sum_c W[o,c] * Xeff[b,c,n] )
//   Xeff = X (plain) or X*silu(Xg) (glu mode)
//   epi: optional *invrms[n] (computed in-kernel from raw X), +bias[o], +addsrc
// K fixed 256. BM=256 (grid.y = Cout/256), BN=128, BK=16. 512 threads, 16 warps.
__global__ void __launch_bounds__(512, 1)
gemm_h(const float* __restrict__ W, const float* __restrict__ bias,
       const float* __restrict__ X, const float* __restrict__ Xg,
       float* __restrict__ Y, const float* __restrict__ addsrc,
       int invMode, int Cout, int Ntot, long xbstride)
{
    __shared__ __half Wh[2][256][24];     // [m][k], 16 data halves + pad
    __shared__ __half Xh[2][16][136];     // [k][n], padded rows
    __shared__ float invs[128];
    __shared__ float4 part[16][32];

    int b  = blockIdx.z;
    int n0 = blockIdx.x * 128;
    int o0 = blockIdx.y * 256;
    const float* Xb  = X + (size_t)b * xbstride;
    const float* Xgb = Xg ? Xg + (size_t)b * xbstride : nullptr;
    float* Yb = Y + (size_t)b * (size_t)Cout * Ntot;
    const float* Ab = addsrc ? addsrc + (size_t)b * (size_t)Cout * Ntot : nullptr;

    int tid = threadIdx.x;
    int lane = tid & 31, warp = tid >> 5;
    int wm = warp & 7, wn = warp >> 3;      // 8 x 2 warp grid, warp tile 32x64
    int group = lane >> 2, tid4 = lane & 3;

    int wm_ld = tid >> 2;                   // 0..127 (W row within half-tile)
    int wkw   = tid & 3;                    // which float4 along k
    int xk    = tid >> 5;                   // 0..15 (X row = warp)
    int xn4   = (tid & 31) * 4;             // X col group

    float acc[2][8][4];
    #pragma unroll
    for (int mt = 0; mt < 2; mt++)
        #pragma unroll
        for (int nt = 0; nt < 8; nt++)
            #pragma unroll
            for (int r = 0; r < 4; r++) acc[mt][nt][r] = 0.f;

    float4 ssq = make_float4(0.f, 0.f, 0.f, 0.f);
    float4 wreg0, wreg1, xreg;

    // ---- prologue: LDG tile 0 into registers
    {
        const float* wp = W + (size_t)(o0 + wm_ld) * 256 + wkw * 4;
        wreg0 = *(const float4*)wp;
        wreg1 = *(const float4*)(wp + (size_t)128 * 256);
        xreg = *(const float4*)(Xb + (size_t)xk * Ntot + n0 + xn4);
        if (Xgb) {
            float4 g = *(const float4*)(Xgb + (size_t)xk * Ntot + n0 + xn4);
            xreg.x *= g.x / (1.f + __expf(-g.x));
            xreg.y *= g.y / (1.f + __expf(-g.y));
            xreg.z *= g.z / (1.f + __expf(-g.z));
            xreg.w *= g.w / (1.f + __expf(-g.w));
        }
        if (invMode) {
            ssq.x += xreg.x * xreg.x; ssq.y += xreg.y * xreg.y;
            ssq.z += xreg.z * xreg.z; ssq.w += xreg.w * xreg.w;
        }
    }

    #pragma unroll 1
    for (int kt = 0; kt < 16; kt++) {
        int buf = kt & 1;
        // ---- store staged tile to smem (fp32 -> fp16)
        {
            __half2* wr0 = (__half2*)&Wh[buf][wm_ld][0];
            wr0[2 * wkw]     = __floats2half2_rn(wreg0.x, wreg0.y);
            wr0[2 * wkw + 1] = __floats2half2_rn(wreg0.z, wreg0.w);
            __half2* wr1 = (__half2*)&Wh[buf][128 + wm_ld][0];
            wr1[2 * wkw]     = __floats2half2_rn(wreg1.x, wreg1.y);
            wr1[2 * wkw + 1] = __floats2half2_rn(wreg1.z, wreg1.w);
            __half2* xr = (__half2*)&Xh[buf][xk][xn4];
            xr[0] = __floats2half2_rn(xreg.x, xreg.y);
            xr[1] = __floats2half2_rn(xreg.z, xreg.w);
        }
        __syncthreads();
        // ---- LDG next tile (overlaps MMA below)
        if (kt < 15) {
            int k0 = (kt + 1) * 16;
            const float* wp = W + (size_t)(o0 + wm_ld) * 256 + k0 + wkw * 4;
            wreg0 = *(const float4*)wp;
            wreg1 = *(const float4*)(wp + (size_t)128 * 256);
            xreg = *(const float4*)(Xb + (size_t)(k0 + xk) * Ntot + n0 + xn4);
            if (Xgb) {
                float4 g = *(const float4*)(Xgb + (size_t)(k0 + xk) * Ntot + n0 + xn4);
                xreg.x *= g.x / (1.f + __expf(-g.x));
                xreg.y *= g.y / (1.f + __expf(-g.y));
                xreg.z *= g.z / (1.f + __expf(-g.z));
                xreg.w *= g.w / (1.f + __expf(-g.w));
            }
            if (invMode) {
                ssq.x += xreg.x * xreg.x; ssq.y += xreg.y * xreg.y;
                ssq.z += xreg.z * xreg.z; ssq.w += xreg.w * xreg.w;
            }
        }
        // ---- fragments + MMA
        unsigned a[2][4];
        #pragma unroll
        for (int mt = 0; mt < 2; mt++) {
            int row = wm * 32 + mt * 16 + (lane & 15);
            unsigned addr = sptr(&Wh[buf][row][(lane >> 4) * 8]);
            ldmx4(a[mt], addr);
        }
        #pragma unroll
        for (int nt = 0; nt < 8; nt++) {
            unsigned baddr = sptr(&Xh[buf][lane & 15][wn * 64 + nt * 8]);
            unsigned b0, b1;
            ldmx2t(b0, b1, baddr);
            mma_h(acc[0][nt], a[0], b0, b1);
            mma_h(acc[1][nt], a[1], b0, b1);
        }
    }

    // ---- in-kernel invrms (colscale applied in epilogue)
    if (invMode) {
        part[xk][tid & 31] = ssq;
        __syncthreads();
        if (tid < 32) {
            float4 s = part[0][tid];
            #pragma unroll
            for (int r = 1; r < 16; r++) {
                float4 p = part[r][tid];
                s.x += p.x; s.y += p.y; s.z += p.z; s.w += p.w;
            }
            invs[tid * 4 + 0] = rsqrtf(s.x * (1.f / CC) + EPSV);
            invs[tid * 4 + 1] = rsqrtf(s.y * (1.f / CC) + EPSV);
            invs[tid * 4 + 2] = rsqrtf(s.z * (1.f / CC) + EPSV);
            invs[tid * 4 + 3] = rsqrtf(s.w * (1.f / CC) + EPSV);
        }
        __syncthreads();
    }

    // ---- epilogue
    #pragma unroll
    for (int mt = 0; mt < 2; mt++) {
        int row = o0 + wm * 32 + mt * 16 + group;
        float bv0 = bias ? bias[row]     : 0.f;
        float bv8 = bias ? bias[row + 8] : 0.f;
        #pragma unroll
        for (int nt = 0; nt < 8; nt++) {
            int cl = wn * 64 + nt * 8 + tid4 * 2;
            int col = n0 + cl;
            size_t i0 = (size_t)row * Ntot + col;
            size_t i8 = (size_t)(row + 8) * Ntot + col;
            float a0 = acc[mt][nt][0], a1 = acc[mt][nt][1];
            float a2 = acc[mt][nt][2], a3 = acc[mt][nt][3];
            if (invMode) {
                float s0 = invs[cl], s1 = invs[cl + 1];
                a0 *= s0; a1 *= s1; a2 *= s0; a3 *= s1;
            }
            float2 v0 = make_float2(a0 + bv0, a1 + bv0);
            float2 v8 = make_float2(a2 + bv8, a3 + bv8);
            if (Ab) {
                float2 r0 = *(const float2*)(Ab + i0);
                float2 r8 = *(const float2*)(Ab + i8);
                v0.x += r0.x; v0.y += r0.y;
                v8.x += r8.x; v8.y += r8.y;
            }
            *(float2*)(Yb + i0) = v0;
            *(float2*)(Yb + i8) = v8;
        }
    }
}

// ---------------- W row-scale precompute ----------------------------------------
__global__ void wscale_kernel(const float* __restrict__ W, const float* __restrict__ rs,
                              float* __restrict__ Wo, int n) {
    int i = blockIdx.x * 256 + threadIdx.x;
    if (i < n) Wo[i] = W[i] * rs[i & 255];
}

// ---------------- small fp32 precompute GEMMs -----------------------------------
__global__ void tn_gemm256(const float* __restrict__ A, const float* __restrict__ B,
                           float* __restrict__ Cm) {
    __shared__ float As[32][33], Bs[32][33];
    int m0 = blockIdx.y * 32, n0 = blockIdx.x * 32;
    int tx = threadIdx.x, ty = threadIdx.y;
    int tid = ty * 16 + tx;
    float acc[2][2] = {{0.f,0.f},{0.f,0.f}};
    for (int r0 = 0; r0 < CC; r0 += 32) {
        #pragma unroll
        for (int i = 0; i < 4; i++) {
            int e = i * 256 + tid;
            int r = e >> 5, c = e & 31;
            As[r][c] = A[(size_t)(r0 + r) * CC + m0 + c];
            Bs[r][c] = B[(size_t)(r0 + r) * CC + n0 + c];
        }
        __syncthreads();
        #pragma unroll
        for (int r = 0; r < 32; r++) {
            float a0 = As[r][ty*2], a1 = As[r][ty*2+1];
            float b0 = Bs[r][tx*2], b1 = Bs[r][tx*2+1];
            acc[0][0] += a0*b0; acc[0][1] += a0*b1;
            acc[1][0] += a1*b0; acc[1][1] += a1*b1;
        }
        __syncthreads();
    }
    #pragma unroll
    for (int i = 0; i < 2; i++)
        #pragma unroll
        for (int j = 0; j < 2; j++)
            Cm[(size_t)(m0 + ty*2 + i) * CC + n0 + tx*2 + j] = acc[i][j];
}

__global__ void nn_gemm256(const float* __restrict__ A, const float* __restrict__ B,
                           float* __restrict__ Cm) {
    __shared__ float As[32][33], Bs[32][33];
    int m0 = blockIdx.y * 32, n0 = blockIdx.x * 32;
    int tx = threadIdx.x, ty = threadIdx.y;
    int tid = ty * 16 + tx;
    float acc[2][2] = {{0.f,0.f},{0.f,0.f}};
    for (int r0 = 0; r0 < CC; r0 += 32) {
        #pragma unroll
        for (int i = 0; i < 4; i++) {
            int e = i * 256 + tid;
            int a = e >> 5, c = e & 31;
            As[a][c] = A[(size_t)(m0 + a) * CC + r0 + c];
            Bs[a][c] = B[(size_t)(r0 + a) * CC + n0 + c];
        }
        __syncthreads();
        #pragma unroll
        for (int r = 0; r < 32; r++) {
            float a0 = As[ty*2][r], a1 = As[ty*2+1][r];
            float b0 = Bs[r][tx*2], b1 = Bs[r][tx*2+1];
            acc[0][0] += a0*b0; acc[0][1] += a0*b1;
            acc[1][0] += a1*b0; acc[1][1] += a1*b1;
        }
        __syncthreads();
    }
    #pragma unroll
    for (int i = 0; i < 2; i++)
        #pragma unroll
        for (int j = 0; j < 2; j++)
            Cm[(size_t)(m0 + ty*2 + i) * CC + n0 + tx*2 + j] = acc[i][j];
}

__global__ void vec_pre_kernel(const float* __restrict__ qw, const float* __restrict__ qb,
                               const float* __restrict__ kw, const float* __restrict__ kb,
                               const float* __restrict__ ow, const float* __restrict__ ob,
                               const float* __restrict__ vb) {
    int j = threadIdx.x;
    float su = 0.f, sw = 0.f, sb = 0.f;
    for (int o = 0; o < CC; o++) {
        su += qb[o] * kw[(size_t)o * CC + j];
        sw += qw[(size_t)o * CC + j] * kb[o];
        sb += ow[(size_t)j * CC + o] * vb[o];
    }
    g_u[j] = su;
    g_w2[j] = sw;
    g_bias2[j] = sb + ob[j];
    if (j == 0) {
        float s0 = 0.f;
        for (int o = 0; o < CC; o++) s0 += qb[o] * kb[o];
        g_misc[0] = s0;
    }
}

// ---------------- depthwise 3x3 causal conv + SiLU, 8 t per block ---------------
#define TB 8
__global__ void dwconv8_kernel(const float* __restrict__ dww, const float* __restrict__ dwb,
                               float* __restrict__ emb) {
    int nblk = TT / TB;
    long idx = blockIdx.x;
    int tb = (int)(idx % nblk);
    long bc = idx / nblk;
    int c = (int)(bc % CC);
    int t0 = tb * TB;
    int f = threadIdx.x;
    __shared__ float rows[TB + 2][FF + 2];
    size_t chbase = (size_t)bc * TT * FF;
    #pragma unroll
    for (int r = 0; r < TB + 2; r++) {
        int tt = t0 - 2 + r;
        rows[r][f + 1] = (tt >= 0) ? g_emb0[chbase + (size_t)tt * FF + f] : 0.f;
        if (f == 0) { rows[r][0] = 0.f; rows[r][FF + 1] = 0.f; }
    }
    __syncthreads();
    float w[9];
    #pragma unroll
    for (int i = 0; i < 9; i++) w[i] = dww[c * 9 + i];
    float bv = dwb[c];
    #pragma unroll
    for (int r = 0; r < TB; r++) {
        float s = bv;
        #pragma unroll
        for (int dt = 0; dt < 3; dt++)
            #pragma unroll
            for (int df = 0; df < 3; df++)
                s += w[dt * 3 + df] * rows[r + dt][f + df];
        s = s / (1.f + __expf(-s));
        emb[chbase + (size_t)(t0 + r) * FF + f] = s;
    }
}

// ---------------- qseed = emb @ basis^T (+ fused colt) --------------------------
__global__ void __launch_bounds__(256)
qseed_kernel(const float* __restrict__ A, const float* __restrict__ Bm,
             float* __restrict__ Y) {
    __shared__ float As[256][33];
    __shared__ __align__(16) float Bs[32][36];
    __shared__ float w2s[256];
    int bt = blockIdx.x;
    int b = bt / TT, t = bt % TT;
    size_t aframe = ((size_t)b * CC * TT + t) * FF;
    size_t yframe = ((size_t)b * CC * TT + t) * KK;
    int tid = threadIdx.x;
    w2s[tid] = g_w2[tid];

    ull acc2[16];
    #pragma unroll
    for (int j = 0; j < 16; j++) acc2[j] = pack2(0.f, 0.f);

    for (int fc = 0; fc < FF; fc += 32) {
        #pragma unroll
        for (int i = 0; i < 32; i++) {
            int e = i * 256 + tid;
            int c = e >> 5, ff = e & 31;
            As[c][ff] = A[aframe + (size_t)c * TT * FF + fc + ff];
        }
        #pragma unroll
        for (int i = 0; i < 4; i++) {
            int e = i * 256 + tid;
            int k = e >> 5, ff = e & 31;
            Bs[ff][k] = Bm[(size_t)k * FF + fc + ff];
        }
        __syncthreads();
        #pragma unroll
        for (int ff = 0; ff < 32; ff++) {
            float av = As[tid][ff];
            ull av2 = pack2(av, av);
            const ulonglong2* brow = (const ulonglong2*)&Bs[ff][0];
            #pragma unroll
            for (int j = 0; j < 8; j++) {
                ulonglong2 bv = brow[j];
                acc2[2*j]   = fma2(av2, bv.x, acc2[2*j]);
                acc2[2*j+1] = fma2(av2, bv.y, acc2[2*j+1]);
            }
        }
        __syncthreads();
    }
    #pragma unroll
    for (int j = 0; j < 16; j++) {
        float lo, hi;
        unpack2(acc2[j], lo, hi);
        As[tid][2*j] = lo;
        As[tid][2*j+1] = hi;
    }
    __syncthreads();
    #pragma unroll
    for (int i = 0; i < 32; i++) {
        int e = i * 256 + tid;
        int c = e >> 5, k = e & 31;
        Y[yframe + (size_t)c * TT * KK + k] = As[c][k];
    }
    if (tid < 32) {
        float s = 0.f;
        #pragma unroll 8
        for (int c = 0; c < CC; c++) s += w2s[c] * As[c][tid];
        g_colt[bt * KK + tid] = s + g_misc[0];
    }
}

// ---------------- fused scores + softmax + pooled --------------------------------
__global__ void __launch_bounds__(256)
attn_fused_kernel(const float* __restrict__ Q2, const float* __restrict__ emb,
                  const float* __restrict__ rb,
                  const float* __restrict__ ssp, const float* __restrict__ psp,
                  float* __restrict__ pooled) {
    __shared__ __align__(16) float Sf[256][36];
    __shared__ float As[256][9];
    __shared__ float us[256];
    __shared__ float colts[32];

    int bt = blockIdx.x;
    int b = bt / TT, t = bt % TT;
    size_t qframe = ((size_t)b * CC * TT + t) * KK;
    size_t eframe = ((size_t)b * CC * TT + t) * FF;
    size_t yframe = qframe;
    int tid = threadIdx.x;
    int lane = tid & 31, warp = tid >> 5;

    ull* qs2 = (ull*)&Sf[0][0];
    #pragma unroll
    for (int i = 0; i < 8; i++) {
        int e = i * 256 + tid;
        int c = e >> 3, j = e & 7;
        float4 v = *(const float4*)(Q2 + qframe + (size_t)c * TT * KK + j * 4);
        qs2[c * 16 + j * 2]     = pack2(v.x, v.y);
        qs2[c * 16 + j * 2 + 1] = pack2(v.z, v.w);
    }
    us[tid] = g_u[tid];
    if (tid < 32) colts[tid] = g_colt[bt * KK + tid];
    __syncthreads();

    int f = tid;
    float acc_u = 0.f;
    ull acc2[16];
    #pragma unroll
    for (int j = 0; j < 16; j++) acc2[j] = pack2(0.f, 0.f);
    #pragma unroll 4
    for (int c = 0; c < CC; c++) {
        float kv = emb[eframe + (size_t)c * TT * FF + f];
        acc_u = fmaf(us[c], kv, acc_u);
        ull kv2 = pack2(kv, kv);
        const ulonglong2* qrow = (const ulonglong2*)&qs2[c * 16];
        #pragma unroll
        for (int j = 0; j < 8; j++) {
            ulonglong2 qv = qrow[j];
            acc2[2*j]   = fma2(qv.x, kv2, acc2[2*j]);
            acc2[2*j+1] = fma2(qv.y, kv2, acc2[2*j+1]);
        }
    }
    float ss = *ssp, ps = *psp;
    float vals[32];
    #pragma unroll
    for (int j = 0; j < 16; j++) unpack2(acc2[j], vals[2*j], vals[2*j+1]);
    __syncthreads();
    #pragma unroll
    for (int k = 0; k < 32; k++)
        Sf[f][k] = ss * (vals[k] + acc_u + colts[k]) + rb[k * FF + f] * ps;
    __syncthreads();

    #pragma unroll
    for (int rr = 0; rr < 4; rr++) {
        int k = warp * 4 + rr;
        float v[8];
        float m = -1e30f;
        #pragma unroll
        for (int i = 0; i < 8; i++) {
            v[i] = Sf[lane + 32 * i][k];
            m = fmaxf(m, v[i]);
        }
        #pragma unroll
        for (int o = 16; o; o >>= 1) m = fmaxf(m, __shfl_xor_sync(0xffffffffu, m, o));
        float s = 0.f;
        #pragma unroll
        for (int i = 0; i < 8; i++) { v[i] = __expf(v[i] - m); s += v[i]; }
        #pragma unroll
        for (int o = 16; o; o >>= 1) s += __shfl_xor_sync(0xffffffffu, s, o);
        float inv = 1.f / s;
        #pragma unroll
        for (int i = 0; i < 8; i++)
            Sf[lane + 32 * i][k] = v[i] * inv;
    }
    __syncthreads();

    #pragma unroll
    for (int j = 0; j < 16; j++) acc2[j] = pack2(0.f, 0.f);
    for (int fc = 0; fc < FF; fc += 8) {
        #pragma unroll
        for (int i = 0; i < 8; i++) {
            int e = i * 256 + tid;
            int c = e >> 3, ff = e & 7;
            As[c][ff] = emb[eframe + (size_t)c * TT * FF + fc + ff];
        }
        __syncthreads();
        #pragma unroll
        for (int ff = 0; ff < 8; ff++) {
            float av = As[tid][ff];
            ull av2 = pack2(av, av);
            const ulonglong2* wrow = (const ulonglong2*)&Sf[fc + ff][0];
            #pragma unroll
            for (int j = 0; j < 8; j++) {
                ulonglong2 wv = wrow[j];
                acc2[2*j]   = fma2(av2, wv.x, acc2[2*j]);
                acc2[2*j+1] = fma2(av2, wv.y, acc2[2*j+1]);
            }
        }
        __syncthreads();
    }
    #pragma unroll
    for (int j = 0; j < 16; j++) {
        float lo, hi;
        unpack2(acc2[j], lo, hi);
        Sf[tid][2*j] = lo;
        Sf[tid][2*j+1] = hi;
    }
    __syncthreads();
    #pragma unroll
    for (int i = 0; i < 32; i++) {
        int e = i * 256 + tid;
        int c = e >> 5, k = e & 31;
        pooled[yframe + (size_t)c * TT * KK + k] = Sf[c][k];
    }
}

// ---------------- host launcher --------------------------------------------------
extern "C" void kernel_launch(void* const* d_in, const int* in_sizes, int n_in,
                              void* d_out, int out_size) {
    const float* x          = (const float*)d_in[0];
    const float* pre_norm_w = (const float*)d_in[1];
    const float* pre_pw_w   = (const float*)d_in[2];
    const float* pre_pw_b   = (const float*)d_in[3];
    const float* pre_dw_w   = (const float*)d_in[4];
    const float* pre_dw_b   = (const float*)d_in[5];
    const float* q_w        = (const float*)d_in[6];
    const float* q_b        = (const float*)d_in[7];
    const float* k_w        = (const float*)d_in[8];
    const float* k_b        = (const float*)d_in[9];
    const float* v_w        = (const float*)d_in[10];
    const float* v_b        = (const float*)d_in[11];
    const float* out_w      = (const float*)d_in[12];
    const float* out_b      = (const float*)d_in[13];
    const float* ffn_norm_w = (const float*)d_in[14];
    const float* ffn_in_w   = (const float*)d_in[15];
    const float* ffn_in_b   = (const float*)d_in[16];
    const float* ffn_out_w  = (const float*)d_in[17];
    const float* ffn_out_b  = (const float*)d_in[18];
    const float* score_scale= (const float*)d_in[19];
    const float* prior_scale= (const float*)d_in[20];
    const float* query_basis= (const float*)d_in[21];
    const float* routing_bias=(const float*)d_in[22];

    float* out        = (float*)d_out;
    float* out_hidden = out;
    float* out_emb    = out + (size_t)BB * CC * TT * KK;

    float *emb0, *qseed, *q2, *pooled, *hidden, *hffn;
    float *P, *OV, *Wp, *Wf, *bias2;
    cudaGetSymbolAddress((void**)&emb0,   g_emb0);
    cudaGetSymbolAddress((void**)&qseed,  g_qseed);
    cudaGetSymbolAddress((void**)&q2,     g_q2);
    cudaGetSymbolAddress((void**)&pooled, g_pooled);
    cudaGetSymbolAddress((void**)&hidden, g_hidden);
    cudaGetSymbolAddress((void**)&hffn,   g_hffn);
    cudaGetSymbolAddress((void**)&P,      g_P);
    cudaGetSymbolAddress((void**)&OV,     g_OV);
    cudaGetSymbolAddress((void**)&Wp,     g_Wp);
    cudaGetSymbolAddress((void**)&Wf,     g_Wf);
    cudaGetSymbolAddress((void**)&bias2,  g_bias2);

    const int NBT = BB * TT;       // 800
    const int NF  = TT * FF;       // 102400
    const int NK  = TT * KK;       // 12800

    // precompute
    wscale_kernel<<<256, 256>>>(pre_pw_w, pre_norm_w, Wp, CC*CC);
    wscale_kernel<<<512, 256>>>(ffn_in_w, ffn_norm_w, Wf, 2*CC*CC);
    tn_gemm256<<<dim3(8, 8), dim3(16, 16)>>>(k_w, q_w, P);
    nn_gemm256<<<dim3(8, 8), dim3(16, 16)>>>(out_w, v_w, OV);
    vec_pre_kernel<<<1, 256>>>(q_w, q_b, k_w, k_b, out_w, out_b, v_b);

    // 1. pre pw with fused RMSNorm (sumsq in-kernel, colscale in epilogue)
    gemm_h<<<dim3(NF/128, 1, BB), 512>>>(Wp, pre_pw_b, x, nullptr, emb0, nullptr,
                                         1, CC, NF, (long)CC * NF);
    // 2. depthwise conv + SiLU -> emb (into d_out)
    dwconv8_kernel<<<(long)BB*CC*(TT/TB), FF>>>(pre_dw_w, pre_dw_b, out_emb);
    // 3. qseed (+colt fused)
    qseed_kernel<<<NBT, 256>>>(out_emb, query_basis, qseed);
    // 4. q2 = P @ qseed
    gemm_h<<<dim3(NK/128, 1, BB), 512>>>(P, nullptr, qseed, nullptr, q2, nullptr,
                                         0, CC, NK, (long)CC * NK);
    // 5. fused scores + softmax + pooled
    attn_fused_kernel<<<NBT, 256>>>(q2, out_emb, routing_bias,
                                    score_scale, prior_scale, pooled);
    // 6. hidden = OV @ pooled + bias2
    gemm_h<<<dim3(NK/128, 1, BB), 512>>>(OV, bias2, pooled, nullptr, hidden, nullptr,
                                         0, CC, NK, (long)CC * NK);
    // 7. ffn_in with fused RMSNorm (rms2 in-kernel)
    gemm_h<<<dim3(NK/128, 2, BB), 512>>>(Wf, ffn_in_b, hidden, nullptr, hffn, nullptr,
                                         1, 2*CC, NK, (long)CC * NK);
    // 8. ffn_out with fused GLU load + residual -> d_out
    gemm_h<<<dim3(NK/128, 1, BB), 512>>>(ffn_out_w, ffn_out_b, hffn, hffn + (size_t)CC * NK,
                                         out_hidden, hidden,
                                         0, CC, NK, (long)2 * CC * NK);
}

// round 7
// speedup vs baseline: 7.2592x; 1.4013x over previous
#include <cuda_runtime.h>
#include <cuda_fp16.h>
#include <math.h>

#define BB 2
#define CC 256
#define TT 400
#define FF 256
#define KK 32
#define EPSV 1e-6f

typedef unsigned long long ull;

// ---------------- scratch ------------------------------------------------------
__device__ float g_emb0   [(size_t)BB*CC*TT*FF];   // used as fp16 (half the space)
__device__ float g_qseed  [(size_t)BB*CC*TT*KK];
__device__ float g_q2     [(size_t)BB*CC*TT*KK];
__device__ float g_pooled [(size_t)BB*CC*TT*KK];
__device__ float g_hidden [(size_t)BB*CC*TT*KK];
__device__ float g_hffn   [(size_t)BB*2*CC*TT*KK];
__device__ float g_P      [CC*CC];
__device__ float g_OV     [CC*CC];
__device__ float g_Wp     [CC*CC];
__device__ float g_Wf     [2*CC*CC];
__device__ float g_u      [CC];
__device__ float g_w2     [CC];
__device__ float g_bias2  [CC];
__device__ float g_colt   [BB*TT*KK];
__device__ float g_misc   [4];

// ---------------- helpers ------------------------------------------------------
__device__ __forceinline__ unsigned sptr(const void* p) {
    return (unsigned)__cvta_generic_to_shared(p);
}
__device__ __forceinline__ void ldmx4(unsigned* a, unsigned addr) {
    asm volatile("ldmatrix.sync.aligned.m8n8.x4.shared.b16 {%0,%1,%2,%3}, [%4];"
        : "=r"(a[0]), "=r"(a[1]), "=r"(a[2]), "=r"(a[3]) : "r"(addr));
}
__device__ __forceinline__ void ldmx2t(unsigned& b0, unsigned& b1, unsigned addr) {
    asm volatile("ldmatrix.sync.aligned.m8n8.x2.trans.shared.b16 {%0,%1}, [%2];"
        : "=r"(b0), "=r"(b1) : "r"(addr));
}
__device__ __forceinline__ void mma_h(float* c, const unsigned* a, unsigned b0, unsigned b1) {
    asm volatile("mma.sync.aligned.m16n8k16.row.col.f32.f16.f16.f32 "
        "{%0,%1,%2,%3}, {%4,%5,%6,%7}, {%8,%9}, {%0,%1,%2,%3};"
        : "+f"(c[0]), "+f"(c[1]), "+f"(c[2]), "+f"(c[3])
        : "r"(a[0]), "r"(a[1]), "r"(a[2]), "r"(a[3]), "r"(b0), "r"(b1));
}

// ---------------- unified fp16 tensor-core GEMM --------------------------------
// Y[b,o,n] = epi( sum_c W[o,c] * Xeff[b,c,n] ); Xeff = X or X*silu(Xg)
// epi: optional *invrms[n] (in-kernel sumsq of Xeff), +bias, +addsrc; fp32 or fp16 out
__global__ void __launch_bounds__(512, 1)
gemm_h(const float* __restrict__ W, const float* __restrict__ bias,
       const float* __restrict__ X, const float* __restrict__ Xg,
       float* __restrict__ Y, __half* __restrict__ Yh,
       const float* __restrict__ addsrc,
       int invMode, int Cout, int Ntot, long xbstride)
{
    __shared__ __half Wh[2][256][24];
    __shared__ __half Xh[2][16][136];
    __shared__ float invs[128];
    __shared__ float4 part[16][32];

    int b  = blockIdx.z;
    int n0 = blockIdx.x * 128;
    int o0 = blockIdx.y * 256;
    const float* Xb  = X + (size_t)b * xbstride;
    const float* Xgb = Xg ? Xg + (size_t)b * xbstride : nullptr;
    float* Yb  = Y  ? Y  + (size_t)b * (size_t)Cout * Ntot : nullptr;
    __half* Yhb = Yh ? Yh + (size_t)b * (size_t)Cout * Ntot : nullptr;
    const float* Ab = addsrc ? addsrc + (size_t)b * (size_t)Cout * Ntot : nullptr;

    int tid = threadIdx.x;
    int lane = tid & 31, warp = tid >> 5;
    int wm = warp & 7, wn = warp >> 3;
    int group = lane >> 2, tid4 = lane & 3;

    int wm_ld = tid >> 2;
    int wkw   = tid & 3;
    int xk    = tid >> 5;
    int xn4   = (tid & 31) * 4;

    float acc[2][8][4];
    #pragma unroll
    for (int mt = 0; mt < 2; mt++)
        #pragma unroll
        for (int nt = 0; nt < 8; nt++)
            #pragma unroll
            for (int r = 0; r < 4; r++) acc[mt][nt][r] = 0.f;

    float4 ssq = make_float4(0.f, 0.f, 0.f, 0.f);
    float4 wreg0, wreg1, xreg;

    {
        const float* wp = W + (size_t)(o0 + wm_ld) * 256 + wkw * 4;
        wreg0 = *(const float4*)wp;
        wreg1 = *(const float4*)(wp + (size_t)128 * 256);
        xreg = *(const float4*)(Xb + (size_t)xk * Ntot + n0 + xn4);
        if (Xgb) {
            float4 g = *(const float4*)(Xgb + (size_t)xk * Ntot + n0 + xn4);
            xreg.x *= g.x / (1.f + __expf(-g.x));
            xreg.y *= g.y / (1.f + __expf(-g.y));
            xreg.z *= g.z / (1.f + __expf(-g.z));
            xreg.w *= g.w / (1.f + __expf(-g.w));
        }
        if (invMode) {
            ssq.x += xreg.x * xreg.x; ssq.y += xreg.y * xreg.y;
            ssq.z += xreg.z * xreg.z; ssq.w += xreg.w * xreg.w;
        }
    }

    #pragma unroll 1
    for (int kt = 0; kt < 16; kt++) {
        int buf = kt & 1;
        {
            __half2* wr0 = (__half2*)&Wh[buf][wm_ld][0];
            wr0[2 * wkw]     = __floats2half2_rn(wreg0.x, wreg0.y);
            wr0[2 * wkw + 1] = __floats2half2_rn(wreg0.z, wreg0.w);
            __half2* wr1 = (__half2*)&Wh[buf][128 + wm_ld][0];
            wr1[2 * wkw]     = __floats2half2_rn(wreg1.x, wreg1.y);
            wr1[2 * wkw + 1] = __floats2half2_rn(wreg1.z, wreg1.w);
            __half2* xr = (__half2*)&Xh[buf][xk][xn4];
            xr[0] = __floats2half2_rn(xreg.x, xreg.y);
            xr[1] = __floats2half2_rn(xreg.z, xreg.w);
        }
        __syncthreads();
        if (kt < 15) {
            int k0 = (kt + 1) * 16;
            const float* wp = W + (size_t)(o0 + wm_ld) * 256 + k0 + wkw * 4;
            wreg0 = *(const float4*)wp;
            wreg1 = *(const float4*)(wp + (size_t)128 * 256);
            xreg = *(const float4*)(Xb + (size_t)(k0 + xk) * Ntot + n0 + xn4);
            if (Xgb) {
                float4 g = *(const float4*)(Xgb + (size_t)(k0 + xk) * Ntot + n0 + xn4);
                xreg.x *= g.x / (1.f + __expf(-g.x));
                xreg.y *= g.y / (1.f + __expf(-g.y));
                xreg.z *= g.z / (1.f + __expf(-g.z));
                xreg.w *= g.w / (1.f + __expf(-g.w));
            }
            if (invMode) {
                ssq.x += xreg.x * xreg.x; ssq.y += xreg.y * xreg.y;
                ssq.z += xreg.z * xreg.z; ssq.w += xreg.w * xreg.w;
            }
        }
        unsigned a[2][4];
        #pragma unroll
        for (int mt = 0; mt < 2; mt++) {
            int row = wm * 32 + mt * 16 + (lane & 15);
            ldmx4(a[mt], sptr(&Wh[buf][row][(lane >> 4) * 8]));
        }
        #pragma unroll
        for (int nt = 0; nt < 8; nt++) {
            unsigned b0, b1;
            ldmx2t(b0, b1, sptr(&Xh[buf][lane & 15][wn * 64 + nt * 8]));
            mma_h(acc[0][nt], a[0], b0, b1);
            mma_h(acc[1][nt], a[1], b0, b1);
        }
    }

    if (invMode) {
        part[xk][tid & 31] = ssq;
        __syncthreads();
        if (tid < 32) {
            float4 s = part[0][tid];
            #pragma unroll
            for (int r = 1; r < 16; r++) {
                float4 p = part[r][tid];
                s.x += p.x; s.y += p.y; s.z += p.z; s.w += p.w;
            }
            invs[tid * 4 + 0] = rsqrtf(s.x * (1.f / CC) + EPSV);
            invs[tid * 4 + 1] = rsqrtf(s.y * (1.f / CC) + EPSV);
            invs[tid * 4 + 2] = rsqrtf(s.z * (1.f / CC) + EPSV);
            invs[tid * 4 + 3] = rsqrtf(s.w * (1.f / CC) + EPSV);
        }
        __syncthreads();
    }

    #pragma unroll
    for (int mt = 0; mt < 2; mt++) {
        int row = o0 + wm * 32 + mt * 16 + group;
        float bv0 = bias ? bias[row]     : 0.f;
        float bv8 = bias ? bias[row + 8] : 0.f;
        #pragma unroll
        for (int nt = 0; nt < 8; nt++) {
            int cl = wn * 64 + nt * 8 + tid4 * 2;
            int col = n0 + cl;
            size_t i0 = (size_t)row * Ntot + col;
            size_t i8 = (size_t)(row + 8) * Ntot + col;
            float a0 = acc[mt][nt][0], a1 = acc[mt][nt][1];
            float a2 = acc[mt][nt][2], a3 = acc[mt][nt][3];
            if (invMode) {
                float s0 = invs[cl], s1 = invs[cl + 1];
                a0 *= s0; a1 *= s1; a2 *= s0; a3 *= s1;
            }
            float2 v0 = make_float2(a0 + bv0, a1 + bv0);
            float2 v8 = make_float2(a2 + bv8, a3 + bv8);
            if (Ab) {
                float2 r0 = *(const float2*)(Ab + i0);
                float2 r8 = *(const float2*)(Ab + i8);
                v0.x += r0.x; v0.y += r0.y;
                v8.x += r8.x; v8.y += r8.y;
            }
            if (Yhb) {
                *(__half2*)(Yhb + i0) = __floats2half2_rn(v0.x, v0.y);
                *(__half2*)(Yhb + i8) = __floats2half2_rn(v8.x, v8.y);
            } else {
                *(float2*)(Yb + i0) = v0;
                *(float2*)(Yb + i8) = v8;
            }
        }
    }
}

// ---------------- W row-scale precompute ----------------------------------------
__global__ void wscale_kernel(const float* __restrict__ W, const float* __restrict__ rs,
                              float* __restrict__ Wo, int n) {
    int i = blockIdx.x * 256 + threadIdx.x;
    if (i < n) Wo[i] = W[i] * rs[i & 255];
}

// ---------------- merged precompute GEMMs: P (tn) and OV (nn) -------------------
__global__ void pre_gemms(const float* __restrict__ kw, const float* __restrict__ qw,
                          const float* __restrict__ ow, const float* __restrict__ vw,
                          float* __restrict__ P, float* __restrict__ OV) {
    __shared__ float As[32][33], Bs[32][33];
    int mode = blockIdx.z;
    int m0 = blockIdx.y * 32, n0 = blockIdx.x * 32;
    int tx = threadIdx.x, ty = threadIdx.y;
    int tid = ty * 16 + tx;
    const float* A = mode ? ow : kw;
    const float* B = mode ? vw : qw;
    float acc[2][2] = {{0.f,0.f},{0.f,0.f}};
    for (int r0 = 0; r0 < CC; r0 += 32) {
        #pragma unroll
        for (int i = 0; i < 4; i++) {
            int e = i * 256 + tid;
            int a = e >> 5, c = e & 31;
            Bs[a][c] = B[(size_t)(r0 + a) * CC + n0 + c];
            As[a][c] = mode ? A[(size_t)(m0 + a) * CC + r0 + c]
                            : A[(size_t)(r0 + a) * CC + m0 + c];
        }
        __syncthreads();
        if (mode) {
            #pragma unroll
            for (int r = 0; r < 32; r++) {
                float a0 = As[ty*2][r], a1 = As[ty*2+1][r];
                float b0 = Bs[r][tx*2], b1 = Bs[r][tx*2+1];
                acc[0][0] += a0*b0; acc[0][1] += a0*b1;
                acc[1][0] += a1*b0; acc[1][1] += a1*b1;
            }
        } else {
            #pragma unroll
            for (int r = 0; r < 32; r++) {
                float a0 = As[r][ty*2], a1 = As[r][ty*2+1];
                float b0 = Bs[r][tx*2], b1 = Bs[r][tx*2+1];
                acc[0][0] += a0*b0; acc[0][1] += a0*b1;
                acc[1][0] += a1*b0; acc[1][1] += a1*b1;
            }
        }
        __syncthreads();
    }
    float* C = mode ? OV : P;
    #pragma unroll
    for (int i = 0; i < 2; i++)
        #pragma unroll
        for (int j = 0; j < 2; j++)
            C[(size_t)(m0 + ty*2 + i) * CC + n0 + tx*2 + j] = acc[i][j];
}

__global__ void vec_pre_kernel(const float* __restrict__ qw, const float* __restrict__ qb,
                               const float* __restrict__ kw, const float* __restrict__ kb,
                               const float* __restrict__ ow, const float* __restrict__ ob,
                               const float* __restrict__ vb) {
    int j = threadIdx.x;
    float su = 0.f, sw = 0.f, sb = 0.f;
    for (int o = 0; o < CC; o++) {
        su += qb[o] * kw[(size_t)o * CC + j];
        sw += qw[(size_t)o * CC + j] * kb[o];
        sb += ow[(size_t)j * CC + o] * vb[o];
    }
    g_u[j] = su;
    g_w2[j] = sw;
    g_bias2[j] = sb + ob[j];
    if (j == 0) {
        float s0 = 0.f;
        for (int o = 0; o < CC; o++) s0 += qb[o] * kb[o];
        g_misc[0] = s0;
    }
}

// ---------------- depthwise 3x3 causal conv + SiLU (fp16 input) -----------------
#define TB 8
__global__ void dwconv8_kernel(const __half* __restrict__ src,
                               const float* __restrict__ dww, const float* __restrict__ dwb,
                               float* __restrict__ emb) {
    int nblk = TT / TB;
    long idx = blockIdx.x;
    int tb = (int)(idx % nblk);
    long bc = idx / nblk;
    int c = (int)(bc % CC);
    int t0 = tb * TB;
    int f = threadIdx.x;
    __shared__ float rows[TB + 2][FF + 2];
    size_t chbase = (size_t)bc * TT * FF;
    #pragma unroll
    for (int r = 0; r < TB + 2; r++) {
        int tt = t0 - 2 + r;
        rows[r][f + 1] = (tt >= 0) ? __half2float(src[chbase + (size_t)tt * FF + f]) : 0.f;
        if (f == 0) { rows[r][0] = 0.f; rows[r][FF + 1] = 0.f; }
    }
    __syncthreads();
    float w[9];
    #pragma unroll
    for (int i = 0; i < 9; i++) w[i] = dww[c * 9 + i];
    float bv = dwb[c];
    #pragma unroll
    for (int r = 0; r < TB; r++) {
        float s = bv;
        #pragma unroll
        for (int dt = 0; dt < 3; dt++)
            #pragma unroll
            for (int df = 0; df < 3; df++)
                s += w[dt * 3 + df] * rows[r + dt][f + df];
        s = s / (1.f + __expf(-s));
        emb[chbase + (size_t)(t0 + r) * FF + f] = s;
    }
}

// ---------------- qseed: batched skinny GEMM on tensor cores --------------------
// Y[row, k] = sum_f emb_flat[row, f] * basis[k, f];  rows = B*C*T
__global__ void __launch_bounds__(256, 2)
qseed_mma_kernel(const float* __restrict__ emb, const float* __restrict__ basis,
                 float* __restrict__ Y)
{
    __shared__ __half Ah[2][128][40];
    __shared__ __half Bh[256 * 40];      // [f][k], flat
    long row0 = (long)blockIdx.x * 128;
    int tid = threadIdx.x;
    int lane = tid & 31, warp = tid >> 5;
    int group = lane >> 2, tid4 = lane & 3;

    // basis -> Bh[f*40 + k] fp16 (transposed)
    #pragma unroll
    for (int i = 0; i < 8; i++) {
        int e = i * 256 + tid;
        int k = e >> 6, f4 = e & 63;
        float4 v = *(const float4*)(basis + (size_t)k * 256 + f4 * 4);
        Bh[(f4 * 4 + 0) * 40 + k] = __float2half(v.x);
        Bh[(f4 * 4 + 1) * 40 + k] = __float2half(v.y);
        Bh[(f4 * 4 + 2) * 40 + k] = __float2half(v.z);
        Bh[(f4 * 4 + 3) * 40 + k] = __float2half(v.w);
    }

    float acc[4][4];
    #pragma unroll
    for (int nt = 0; nt < 4; nt++)
        #pragma unroll
        for (int r = 0; r < 4; r++) acc[nt][r] = 0.f;

    float4 areg[4];
    #pragma unroll
    for (int i = 0; i < 4; i++) {
        int e = i * 256 + tid;
        int m = e >> 3, j = e & 7;
        areg[i] = *(const float4*)(emb + (row0 + m) * 256 + j * 4);
    }

    #pragma unroll 1
    for (int kt = 0; kt < 8; kt++) {
        int buf = kt & 1;
        #pragma unroll
        for (int i = 0; i < 4; i++) {
            int e = i * 256 + tid;
            int m = e >> 3, j = e & 7;
            __half2* d = (__half2*)&Ah[buf][m][j * 4];
            d[0] = __floats2half2_rn(areg[i].x, areg[i].y);
            d[1] = __floats2half2_rn(areg[i].z, areg[i].w);
        }
        __syncthreads();
        if (kt < 7) {
            int ksn = (kt + 1) * 32;
            #pragma unroll
            for (int i = 0; i < 4; i++) {
                int e = i * 256 + tid;
                int m = e >> 3, j = e & 7;
                areg[i] = *(const float4*)(emb + (row0 + m) * 256 + ksn + j * 4);
            }
        }
        #pragma unroll
        for (int kk = 0; kk < 2; kk++) {
            unsigned a[4];
            ldmx4(a, sptr(&Ah[buf][warp * 16 + (lane & 15)][kk * 16 + (lane >> 4) * 8]));
            #pragma unroll
            for (int nt = 0; nt < 4; nt++) {
                unsigned b0, b1;
                ldmx2t(b0, b1, sptr(&Bh[(kt * 32 + kk * 16 + (lane & 15)) * 40 + nt * 8]));
                mma_h(acc[nt], a, b0, b1);
            }
        }
    }

    long r1 = row0 + warp * 16 + group;
    #pragma unroll
    for (int nt = 0; nt < 4; nt++) {
        int col = nt * 8 + tid4 * 2;
        *(float2*)(Y + r1 * 32 + col)       = make_float2(acc[nt][0], acc[nt][1]);
        *(float2*)(Y + (r1 + 8) * 32 + col) = make_float2(acc[nt][2], acc[nt][3]);
    }
}

// ---------------- colt: colt[bt][k] = sum_c w2[c]*qseed[b,c,t,k] + s0 ----------
__global__ void colt_kernel(const float* __restrict__ qs) {
    __shared__ float part[8][32];
    int bt = blockIdx.x;
    int b = bt / TT, t = bt % TT;
    size_t base = ((size_t)b * CC * TT + t) * KK;
    int k = threadIdx.x & 31, cg = threadIdx.x >> 5;
    float s = 0.f;
    for (int c = cg; c < CC; c += 8)
        s += g_w2[c] * qs[base + (size_t)c * TT * KK + k];
    part[cg][k] = s;
    __syncthreads();
    if (threadIdx.x < 32) {
        float tot = g_misc[0];
        #pragma unroll
        for (int i = 0; i < 8; i++) tot += part[i][k];
        g_colt[bt * KK + k] = tot;
    }
}

// ---------------- fused attention: scores(MMA) + softmax + pooled(MMA) ----------
// smem: Eh[256][264] fp16 | union{ q2T[48][264] fp16, scoresF[33][264] f32,
//       poolSm[256][34] f32 } | Wt[256][40] fp16
#define ATTN_SMEM (256*264*2 + 34848 + 256*40*2)
__global__ void __launch_bounds__(256, 1)
attn_mma_kernel(const float* __restrict__ Q2, const float* __restrict__ emb,
                const float* __restrict__ rb,
                const float* __restrict__ ssp, const float* __restrict__ psp,
                float* __restrict__ pooled)
{
    extern __shared__ __align__(16) char sm_[];
    __half* Eh = (__half*)sm_;
    char* regU = sm_ + 256 * 264 * 2;
    __half* q2T = (__half*)regU;
    float* scoresF = (float*)regU;
    float* poolSm = (float*)regU;
    __half* Wt = (__half*)(regU + 34848);
    __shared__ float colts[32];

    int bt = blockIdx.x;
    int b = bt / TT, t = bt % TT;
    size_t qframe = ((size_t)b * CC * TT + t) * KK;
    size_t eframe = ((size_t)b * CC * TT + t) * FF;
    int tid = threadIdx.x;
    int lane = tid & 31, warp = tid >> 5;
    int group = lane >> 2, tid4 = lane & 3;

    // ---- load emb frame -> Eh fp16
    #pragma unroll 8
    for (int i = 0; i < 64; i++) {
        int e = i * 256 + tid;
        int c = e >> 6, f4 = e & 63;
        float4 v = *(const float4*)(emb + eframe + (size_t)c * TT * FF + f4 * 4);
        __half2* dst = (__half2*)&Eh[c * 264 + f4 * 4];
        dst[0] = __floats2half2_rn(v.x, v.y);
        dst[1] = __floats2half2_rn(v.z, v.w);
    }
    // ---- zero q2T rows 32..47, then u row (32)
    for (int e = tid; e < 16 * 264; e += 256)
        q2T[32 * 264 + e] = __float2half(0.f);
    q2T[32 * 264 + tid] = __float2half(g_u[tid]);
    // ---- load q2 frame [c][k] -> q2T[k][c] fp16
    #pragma unroll
    for (int i = 0; i < 8; i++) {
        int e = i * 256 + tid;
        int c = e >> 3, j = e & 7;
        float4 v = *(const float4*)(Q2 + qframe + (size_t)c * TT * KK + j * 4);
        q2T[(4*j + 0) * 264 + c] = __float2half(v.x);
        q2T[(4*j + 1) * 264 + c] = __float2half(v.y);
        q2T[(4*j + 2) * 264 + c] = __float2half(v.z);
        q2T[(4*j + 3) * 264 + c] = __float2half(v.w);
    }
    if (tid < 32) colts[tid] = g_colt[bt * KK + tid];
    __syncthreads();

    // ---- pass 1: scores[k(48), f] MMA; warp owns 32 f-columns
    float acc1[3][4][4];
    #pragma unroll
    for (int mt = 0; mt < 3; mt++)
        #pragma unroll
        for (int nt = 0; nt < 4; nt++)
            #pragma unroll
            for (int r = 0; r < 4; r++) acc1[mt][nt][r] = 0.f;

    #pragma unroll 1
    for (int ks = 0; ks < 256; ks += 16) {
        unsigned a[3][4];
        #pragma unroll
        for (int mt = 0; mt < 3; mt++)
            ldmx4(a[mt], sptr(&q2T[(mt * 16 + (lane & 15)) * 264 + ks + (lane >> 4) * 8]));
        #pragma unroll
        for (int nt = 0; nt < 4; nt++) {
            unsigned b0, b1;
            ldmx2t(b0, b1, sptr(&Eh[(ks + (lane & 15)) * 264 + warp * 32 + nt * 8]));
            mma_h(acc1[0][nt], a[0], b0, b1);
            mma_h(acc1[1][nt], a[1], b0, b1);
            mma_h(acc1[2][nt], a[2], b0, b1);
        }
    }
    __syncthreads();   // q2T reads complete; region becomes scoresF

    #pragma unroll
    for (int mt = 0; mt < 2; mt++)
        #pragma unroll
        for (int nt = 0; nt < 4; nt++) {
            int row = mt * 16 + group;
            int col = warp * 32 + nt * 8 + tid4 * 2;
            *(float2*)&scoresF[row * 264 + col]       = make_float2(acc1[mt][nt][0], acc1[mt][nt][1]);
            *(float2*)&scoresF[(row + 8) * 264 + col] = make_float2(acc1[mt][nt][2], acc1[mt][nt][3]);
        }
    if (group == 0) {
        #pragma unroll
        for (int nt = 0; nt < 4; nt++) {
            int col = warp * 32 + nt * 8 + tid4 * 2;
            *(float2*)&scoresF[32 * 264 + col] = make_float2(acc1[2][nt][0], acc1[2][nt][1]);
        }
    }
    __syncthreads();

    // ---- softmax per k; weights -> Wt[f][k] fp16
    float ss = *ssp, ps = *psp;
    #pragma unroll
    for (int rr = 0; rr < 4; rr++) {
        int k = warp * 4 + rr;
        float cv = colts[k];
        float v[8];
        float m = -1e30f;
        #pragma unroll
        for (int i = 0; i < 8; i++) {
            int f = lane + 32 * i;
            float raw = scoresF[k * 264 + f];
            float uu  = scoresF[32 * 264 + f];
            v[i] = ss * (raw + uu + cv) + rb[k * FF + f] * ps;
            m = fmaxf(m, v[i]);
        }
        #pragma unroll
        for (int o = 16; o; o >>= 1) m = fmaxf(m, __shfl_xor_sync(0xffffffffu, m, o));
        float s = 0.f;
        #pragma unroll
        for (int i = 0; i < 8; i++) { v[i] = __expf(v[i] - m); s += v[i]; }
        #pragma unroll
        for (int o = 16; o; o >>= 1) s += __shfl_xor_sync(0xffffffffu, s, o);
        float inv = 1.f / s;
        #pragma unroll
        for (int i = 0; i < 8; i++) {
            int f = lane + 32 * i;
            Wt[f * 40 + k] = __float2half(v[i] * inv);
        }
    }
    __syncthreads();

    // ---- pass 2: pooled[c, k] = sum_f Eh[c,f] * Wt[f,k]; warp owns 32 c-rows
    float acc2[2][4][4];
    #pragma unroll
    for (int mt = 0; mt < 2; mt++)
        #pragma unroll
        for (int nt = 0; nt < 4; nt++)
            #pragma unroll
            for (int r = 0; r < 4; r++) acc2[mt][nt][r] = 0.f;

    #pragma unroll 1
    for (int fs = 0; fs < 256; fs += 16) {
        unsigned a[2][4];
        #pragma unroll
        for (int mt = 0; mt < 2; mt++)
            ldmx4(a[mt], sptr(&Eh[(warp * 32 + mt * 16 + (lane & 15)) * 264 + fs + (lane >> 4) * 8]));
        #pragma unroll
        for (int nt = 0; nt < 4; nt++) {
            unsigned b0, b1;
            ldmx2t(b0, b1, sptr(&Wt[(fs + (lane & 15)) * 40 + nt * 8]));
            mma_h(acc2[0][nt], a[0], b0, b1);
            mma_h(acc2[1][nt], a[1], b0, b1);
        }
    }
    __syncthreads();   // scoresF readers done; region becomes poolSm

    #pragma unroll
    for (int mt = 0; mt < 2; mt++)
        #pragma unroll
        for (int nt = 0; nt < 4; nt++) {
            int row = warp * 32 + mt * 16 + group;
            int col = nt * 8 + tid4 * 2;
            *(float2*)&poolSm[row * 34 + col]       = make_float2(acc2[mt][nt][0], acc2[mt][nt][1]);
            *(float2*)&poolSm[(row + 8) * 34 + col] = make_float2(acc2[mt][nt][2], acc2[mt][nt][3]);
        }
    __syncthreads();
    #pragma unroll
    for (int i = 0; i < 32; i++) {
        int e = i * 256 + tid;
        int c = e >> 5, k = e & 31;
        pooled[qframe + (size_t)c * TT * KK + k] = poolSm[c * 34 + k];
    }
}

// ---------------- host launcher --------------------------------------------------
extern "C" void kernel_launch(void* const* d_in, const int* in_sizes, int n_in,
                              void* d_out, int out_size) {
    const float* x          = (const float*)d_in[0];
    const float* pre_norm_w = (const float*)d_in[1];
    const float* pre_pw_w   = (const float*)d_in[2];
    const float* pre_pw_b   = (const float*)d_in[3];
    const float* pre_dw_w   = (const float*)d_in[4];
    const float* pre_dw_b   = (const float*)d_in[5];
    const float* q_w        = (const float*)d_in[6];
    const float* q_b        = (const float*)d_in[7];
    const float* k_w        = (const float*)d_in[8];
    const float* k_b        = (const float*)d_in[9];
    const float* v_w        = (const float*)d_in[10];
    const float* v_b        = (const float*)d_in[11];
    const float* out_w      = (const float*)d_in[12];
    const float* out_b      = (const float*)d_in[13];
    const float* ffn_norm_w = (const float*)d_in[14];
    const float* ffn_in_w   = (const float*)d_in[15];
    const float* ffn_in_b   = (const float*)d_in[16];
    const float* ffn_out_w  = (const float*)d_in[17];
    const float* ffn_out_b  = (const float*)d_in[18];
    const float* score_scale= (const float*)d_in[19];
    const float* prior_scale= (const float*)d_in[20];
    const float* query_basis= (const float*)d_in[21];
    const float* routing_bias=(const float*)d_in[22];

    float* out        = (float*)d_out;
    float* out_hidden = out;
    float* out_emb    = out + (size_t)BB * CC * TT * KK;

    float *emb0, *qseed, *q2, *pooled, *hidden, *hffn;
    float *P, *OV, *Wp, *Wf, *bias2;
    cudaGetSymbolAddress((void**)&emb0,   g_emb0);
    cudaGetSymbolAddress((void**)&qseed,  g_qseed);
    cudaGetSymbolAddress((void**)&q2,     g_q2);
    cudaGetSymbolAddress((void**)&pooled, g_pooled);
    cudaGetSymbolAddress((void**)&hidden, g_hidden);
    cudaGetSymbolAddress((void**)&hffn,   g_hffn);
    cudaGetSymbolAddress((void**)&P,      g_P);
    cudaGetSymbolAddress((void**)&OV,     g_OV);
    cudaGetSymbolAddress((void**)&Wp,     g_Wp);
    cudaGetSymbolAddress((void**)&Wf,     g_Wf);
    cudaGetSymbolAddress((void**)&bias2,  g_bias2);

    cudaFuncSetAttribute(attn_mma_kernel,
                         cudaFuncAttributeMaxDynamicSharedMemorySize, ATTN_SMEM);

    const int NBT = BB * TT;       // 800
    const int NF  = TT * FF;       // 102400
    const int NK  = TT * KK;       // 12800

    // precompute
    wscale_kernel<<<256, 256>>>(pre_pw_w, pre_norm_w, Wp, CC*CC);
    wscale_kernel<<<512, 256>>>(ffn_in_w, ffn_norm_w, Wf, 2*CC*CC);
    pre_gemms<<<dim3(8, 8, 2), dim3(16, 16)>>>(k_w, q_w, out_w, v_w, P, OV);
    vec_pre_kernel<<<1, 256>>>(q_w, q_b, k_w, k_b, out_w, out_b, v_b);

    // 1. pre pw with fused RMSNorm -> emb0 (fp16 storage)
    gemm_h<<<dim3(NF/128, 1, BB), 512>>>(Wp, pre_pw_b, x, nullptr,
                                         nullptr, (__half*)emb0, nullptr,
                                         1, CC, NF, (long)CC * NF);
    // 2. depthwise conv + SiLU -> emb (into d_out)
    dwconv8_kernel<<<(long)BB*CC*(TT/TB), FF>>>((const __half*)emb0, pre_dw_w, pre_dw_b, out_emb);
    // 3. qseed = emb @ basis^T (batched skinny tensor GEMM over all rows)
    qseed_mma_kernel<<<(BB*CC*TT)/128, 256>>>(out_emb, query_basis, qseed);
    // 4. colt
    colt_kernel<<<NBT, 256>>>(qseed);
    // 5. q2 = P @ qseed
    gemm_h<<<dim3(NK/128, 1, BB), 512>>>(P, nullptr, qseed, nullptr, q2, nullptr, nullptr,
                                         0, CC, NK, (long)CC * NK);
    // 6. fused attention (scores MMA + softmax + pooled MMA)
    attn_mma_kernel<<<NBT, 256, ATTN_SMEM>>>(q2, out_emb, routing_bias,
                                             score_scale, prior_scale, pooled);
    // 7. hidden = OV @ pooled + bias2
    gemm_h<<<dim3(NK/128, 1, BB), 512>>>(OV, bias2, pooled, nullptr, hidden, nullptr, nullptr,
                                         0, CC, NK, (long)CC * NK);
    // 8. ffn_in with fused RMSNorm
    gemm_h<<<dim3(NK/128, 2, BB), 512>>>(Wf, ffn_in_b, hidden, nullptr, hffn, nullptr, nullptr,
                                         1, 2*CC, NK, (long)CC * NK);
    // 9. ffn_out with fused GLU load + residual -> d_out
    gemm_h<<<dim3(NK/128, 1, BB), 512>>>(ffn_out_w, ffn_out_b, hffn, hffn + (size_t)CC * NK,
                                         out_hidden, nullptr, hidden,
                                         0, CC, NK, (long)2 * CC * NK);
}